// round 7
// baseline (speedup 1.0000x reference)
#include <cuda_runtime.h>
#include <math.h>
#include <stdint.h>

#define BATCH 2
#define SEQ   4096
#define DMODEL 256
#define NHEAD 8
#define DHEAD 32
#define DMLP  1024
#define NROW  (BATCH*SEQ)   // 8192

// ---------------- scratch (static device globals; no allocation) -------------
__device__ float g_xn[NROW*DMODEL];
__device__ float g_qkv[NROW*3*DMODEL];
__device__ float g_attn[NROW*DMODEL];
__device__ float g_mlpin[NROW*DMODEL];
__device__ float g_yn[NROW*DMODEL];
__device__ float g_h[NROW*DMLP];
#define WSMALL (DMODEL*DMODEL)        // 65536
#define WBIG   (DMLP*DMODEL)          // 262144
__device__ float g_wr[4*WSMALL + 2*WBIG];   // rounded weights

// inv_freq[i] = 10000^(-i/16) = 10^(-i/4)
__constant__ float c_invfreq[16] = {
    1.0f, 0.5623413251903491f, 0.31622776601683794f, 0.17782794100389228f,
    0.1f, 0.05623413251903491f, 0.031622776601683794f, 0.017782794100389228f,
    0.01f, 0.005623413251903491f, 0.0031622776601683794f, 0.0017782794100389228f,
    0.001f, 0.0005623413251903491f, 0.00031622776601683794f, 0.00017782794100389227f
};

__device__ __forceinline__ float f2tf(float x) {
    uint32_t u;
    asm("cvt.rna.tf32.f32 %0, %1;" : "=r"(u) : "f"(x));
    return __uint_as_float(u);
}
__device__ __forceinline__ void cp16(float* smem_dst, const float* gmem_src) {
    uint32_t s = (uint32_t)__cvta_generic_to_shared(smem_dst);
    asm volatile("cp.async.cg.shared.global [%0], [%1], 16;" :: "r"(s), "l"(gmem_src));
}
#define CP_COMMIT() asm volatile("cp.async.commit_group;")
__device__ __forceinline__ uint32_t saddr(const void* p) {
    return (uint32_t)__cvta_generic_to_shared(p);
}
__device__ __forceinline__ void ldsm_x4(uint32_t* r, uint32_t a) {
    asm volatile("ldmatrix.sync.aligned.m8n8.x4.shared.b16 {%0,%1,%2,%3}, [%4];"
        : "=r"(r[0]), "=r"(r[1]), "=r"(r[2]), "=r"(r[3]) : "r"(a));
}
__device__ __forceinline__ void ldsm_x2(uint32_t* r, uint32_t a) {
    asm volatile("ldmatrix.sync.aligned.m8n8.x2.shared.b16 {%0,%1}, [%2];"
        : "=r"(r[0]), "=r"(r[1]) : "r"(a));
}
__device__ __forceinline__ void mma_tf32(float* d, const uint32_t* a, uint32_t b0, uint32_t b1) {
    asm volatile("mma.sync.aligned.m16n8k8.row.col.f32.tf32.tf32.f32 "
        "{%0,%1,%2,%3}, {%4,%5,%6,%7}, {%8,%9}, {%0,%1,%2,%3};\n"
        : "+f"(d[0]), "+f"(d[1]), "+f"(d[2]), "+f"(d[3])
        : "r"(a[0]), "r"(a[1]), "r"(a[2]), "r"(a[3]), "r"(b0), "r"(b1));
}

// ---------------- weight pre-rounding (rna -> tf32-exact fp32) ----------------
__global__ void round_weights(const float* __restrict__ Wq, const float* __restrict__ Wk,
                              const float* __restrict__ Wv, const float* __restrict__ Wo,
                              const float* __restrict__ W2, const float* __restrict__ W3,
                              float* __restrict__ out)
{
    const int i = blockIdx.x * blockDim.x + threadIdx.x;   // float4 index
    const int n1 = WSMALL / 4;
    const float4* src;
    int local;
    if (i < 4*n1) {
        const float* w4[4] = {Wq, Wk, Wv, Wo};
        src = (const float4*)w4[i / n1];
        local = i % n1;
    } else if (i < 4*n1 + WBIG/4) {
        src = (const float4*)W2; local = i - 4*n1;
    } else {
        src = (const float4*)W3; local = i - 4*n1 - WBIG/4;
    }
    float4 v = src[local];
    v.x = f2tf(v.x); v.y = f2tf(v.y); v.z = f2tf(v.z); v.w = f2tf(v.w);
    ((float4*)out)[i] = v;
}

// ---------------- LayerNorm: one block per row, rounded output ---------------
__global__ void ln_kernel(const float* __restrict__ x, const float* __restrict__ g,
                          const float* __restrict__ b, float* __restrict__ out)
{
    const int row = blockIdx.x;
    const int t   = threadIdx.x;
    const float v = x[row*DMODEL + t];
    __shared__ float red1[8];
    __shared__ float red2[8];

    float s = v;
    #pragma unroll
    for (int o = 16; o > 0; o >>= 1) s += __shfl_xor_sync(0xffffffffu, s, o);
    if ((t & 31) == 0) red1[t >> 5] = s;
    __syncthreads();
    float mean = 0.f;
    #pragma unroll
    for (int i = 0; i < 8; i++) mean += red1[i];
    mean *= (1.0f/DMODEL);
    const float d = v - mean;

    float s2 = d*d;
    #pragma unroll
    for (int o = 16; o > 0; o >>= 1) s2 += __shfl_xor_sync(0xffffffffu, s2, o);
    if ((t & 31) == 0) red2[t >> 5] = s2;
    __syncthreads();
    float var = 0.f;
    #pragma unroll
    for (int i = 0; i < 8; i++) var += red2[i];
    var *= (1.0f/DMODEL);

    out[row*DMODEL + t] = f2tf(d * rsqrtf(var + 1e-5f) * g[t] + b[t]);
}

// ---------------- GEMM (C = A * B^T), tf32 mma, 4-stage cp.async, ldmatrix ---
// Tile 64x128x32, 256 thr, 8 warps 2(m)x4(n), warp 32x32 (MI=2, NJ=4).
enum { EPI_NONE=0, EPI_ROPE=1, EPI_BIAS_GELU=2, EPI_RESID=3, EPI_BIAS_RESID=4, EPI_QKV=5 };

template<int EPI>
__global__ __launch_bounds__(256, 2)
void gemm_v3(const float* __restrict__ A, int lda,
             const float* __restrict__ Bw, int ldb,
             float* __restrict__ C, int ldc, int K,
             const float* __restrict__ bias,
             const float* __restrict__ resid, int ldr)
{
    extern __shared__ float sm[];
    float (*As)[36] = (float(*)[36])sm;               // [4*64][36]
    float (*Bs)[36] = (float(*)[36])(sm + 4*64*36);   // [4*128][36]

    const int tid = threadIdx.x;
    const int w = tid>>5, L = tid&31, gid = L>>2, t = L&3;
    const int wm = w>>2, wn = w&3;
    const int m0 = blockIdx.y * 64;
    const int bx = blockIdx.x;

    const float* Bmat;
    int nlocal0, ncout0;
    if (EPI == EPI_QKV) {
        Bmat = (bx < 2) ? Bw : (bx < 4) ? bias : resid;
        nlocal0 = (bx & 1) * 128;
        ncout0  = bx * 128;
    } else {
        Bmat = Bw;
        nlocal0 = bx * 128;
        ncout0  = nlocal0;
    }

    float acc[2][4][4];
    #pragma unroll
    for (int i = 0; i < 2; i++)
        #pragma unroll
        for (int j = 0; j < 4; j++)
            #pragma unroll
            for (int r = 0; r < 4; r++) acc[i][j][r] = 0.f;

    auto loadA = [&](int stg, int k0) {
        #pragma unroll
        for (int c = 0; c < 2; c++) {
            const int ci = tid*2 + c;
            const int r = ci>>3, cc = (ci&7)*4;
            cp16(&As[stg*64 + r][cc], A + (size_t)(m0+r)*lda + k0 + cc);
        }
    };
    auto loadB = [&](int stg, int k0) {
        #pragma unroll
        for (int c = 0; c < 4; c++) {
            const int ci = tid*4 + c;
            const int r = ci>>3, cc = (ci&7)*4;
            cp16(&Bs[stg*128 + r][cc], Bmat + (size_t)(nlocal0+r)*ldb + k0 + cc);
        }
    };

    loadA(0, 0);  loadB(0, 0);  CP_COMMIT();
    loadA(1, 32); loadB(1, 32); CP_COMMIT();
    loadA(2, 64); loadB(2, 64); CP_COMMIT();

    // ldmatrix lane addressing
    const int rA = (L&7) + ((L>>3)&1)*8;   // + warp row base + mi*16
    const int wA = (L>>4)*4;
    const int rB = (L&7);
    const int wB = ((L>>3)&1)*4;

    const int iters = K/32;
    for (int it = 0; it < iters; it++) {
        asm volatile("cp.async.wait_group 2;");
        __syncthreads();

        const float (*Ac)[36] = (const float(*)[36])(As + (it&3)*64);
        const float (*Bc)[36] = (const float(*)[36])(Bs + (it&3)*128);

        #pragma unroll
        for (int kb = 0; kb < 4; kb++) {
            uint32_t af[2][4];
            #pragma unroll
            for (int mi = 0; mi < 2; mi++)
                ldsm_x4(af[mi], saddr(&Ac[wm*32 + mi*16 + rA][8*kb + wA]));
            #pragma unroll
            for (int nj = 0; nj < 4; nj++) {
                uint32_t bf[2];
                ldsm_x2(bf, saddr(&Bc[wn*32 + nj*8 + rB][8*kb + wB]));
                mma_tf32(acc[0][nj], af[0], bf[0], bf[1]);
                mma_tf32(acc[1][nj], af[1], bf[0], bf[1]);
            }
        }

        if (it + 3 < iters) {
            loadA((it+3)&3, (it+3)*32);
            loadB((it+3)&3, (it+3)*32);
            CP_COMMIT();
        }
    }

    // epilogue
    #pragma unroll
    for (int mi = 0; mi < 2; mi++) {
        #pragma unroll
        for (int half = 0; half < 2; half++) {
            const int gm = m0 + wm*32 + mi*16 + gid + half*8;
            #pragma unroll
            for (int nj = 0; nj < 4; nj++) {
                const int gc = ncout0 + wn*32 + nj*8 + 2*t;   // even
                float v0 = acc[mi][nj][half*2 + 0];
                float v1 = acc[mi][nj][half*2 + 1];

                if (EPI == EPI_QKV) {
                    if (gc < 512) {   // rope on Q and K outputs
                        const int s  = gm & (SEQ - 1);
                        const int dd = gc & (DHEAD - 1);
                        const float ang = (float)s * c_invfreq[dd >> 1];
                        float sn, cs;
                        sincosf(ang, &sn, &cs);
                        const float e = v0, o = v1;
                        v0 = e*cs - o*sn;
                        v1 = o*cs + e*sn;
                    }
                    v0 = f2tf(v0); v1 = f2tf(v1);          // feeds attention mmas
                } else if (EPI == EPI_BIAS_GELU) {
                    float t0 = v0 + bias[gc], t1 = v1 + bias[gc + 1];
                    v0 = f2tf(0.5f * t0 * (1.0f + erff(t0 * 0.7071067811865476f)));
                    v1 = f2tf(0.5f * t1 * (1.0f + erff(t1 * 0.7071067811865476f)));
                } else if (EPI == EPI_RESID) {
                    v0 += resid[(size_t)gm * ldr + gc];      // mlpin stays fp32
                    v1 += resid[(size_t)gm * ldr + gc + 1];
                } else if (EPI == EPI_BIAS_RESID) {
                    v0 += bias[gc]     + resid[(size_t)gm * ldr + gc];
                    v1 += bias[gc + 1] + resid[(size_t)gm * ldr + gc + 1];
                }
                *(float2*)&C[(size_t)gm * ldc + gc] = make_float2(v0, v1);
            }
        }
    }
}

// ---------------- Flash attention, tf32 mma + ldmatrix, cp.async 2-stage -----
// CTA: 128 q-rows, 8 warps (each 16 q-rows x 64 k-cols). K-tile = 64.
__global__ __launch_bounds__(256, 2)
void flash_attn_v3(const float* __restrict__ qkv, float* __restrict__ out)
{
    extern __shared__ float sm[];
    float (*Qs)[36] = (float(*)[36])sm;                                 // [128][36]
    float (*Ks)[36] = (float(*)[36])(sm + 128*36);                      // [2*64][36]
    float (*Vs)[40] = (float(*)[40])(sm + 128*36 + 2*64*36);            // [2*64][40]
    float (*PsA)[68] = (float(*)[68])(sm + 128*36 + 2*64*36 + 2*64*40); // [8*16][68]

    const int tid = threadIdx.x;
    const int w = tid>>5, L = tid&31, gid = L>>2, t = L&3;
    const int b = blockIdx.y >> 3, h = blockIdx.y & 7;
    const int qbase = blockIdx.x * 128;
    const int qw = w * 16;
    float (*Pw)[68] = PsA + w*16;

    const size_t qoff  = (size_t)(b*SEQ + qbase) * 768 + h*32;
    const size_t kvoff = (size_t)(b*SEQ) * 768 + h*32;

    #pragma unroll
    for (int c = 0; c < 4; c++) {
        const int ci = tid*4 + c;
        const int r = ci>>3, cc = (ci&7)*4;
        cp16(&Qs[r][cc], qkv + qoff + (size_t)r*768 + cc);
    }
    auto loadKV = [&](int stg, int kt) {
        #pragma unroll
        for (int c = 0; c < 2; c++) {
            const int ci = tid*2 + c;
            const int r = ci>>3, cc = (ci&7)*4;
            const float* src = qkv + kvoff + (size_t)(kt*64 + r)*768 + cc;
            cp16(&Ks[stg*64 + r][cc], src + 256);
            cp16(&Vs[stg*64 + r][cc], src + 512);
        }
    };
    loadKV(0, 0);
    CP_COMMIT();
    asm volatile("cp.async.wait_group 0;");
    __syncthreads();

    uint32_t qa[4][4];
    #pragma unroll
    for (int kb = 0; kb < 4; kb++) {
        qa[kb][0] = __float_as_uint(Qs[qw + gid    ][8*kb + t]);
        qa[kb][1] = __float_as_uint(Qs[qw + gid + 8][8*kb + t]);
        qa[kb][2] = __float_as_uint(Qs[qw + gid    ][8*kb + t + 4]);
        qa[kb][3] = __float_as_uint(Qs[qw + gid + 8][8*kb + t + 4]);
    }

    // ldmatrix lane addressing
    const int rK = (L&7);
    const int wK = ((L>>3)&1)*4;
    const int rP = (L&7) + ((L>>3)&1)*8;
    const int wP = (L>>4)*4;

    float oacc[4][4];
    #pragma unroll
    for (int j = 0; j < 4; j++)
        #pragma unroll
        for (int r = 0; r < 4; r++) oacc[j][r] = 0.f;
    float mA = -1e30f, mB = -1e30f, lA = 0.f, lB = 0.f;
    const float scale = 0.17677669529663687f;  // 1/sqrt(32)

    for (int kt = 0; kt < SEQ/64; kt++) {
        if (kt > 0) { asm volatile("cp.async.wait_group 0;"); }
        __syncthreads();
        if (kt + 1 < SEQ/64) { loadKV((kt+1)&1, kt+1); CP_COMMIT(); }

        const float (*Kc)[36] = (const float(*)[36])(Ks + (kt&1)*64);
        const float (*Vc)[40] = (const float(*)[40])(Vs + (kt&1)*64);

        // S = Q K^T
        float sa[8][4];
        #pragma unroll
        for (int j = 0; j < 8; j++)
            #pragma unroll
            for (int r = 0; r < 4; r++) sa[j][r] = 0.f;

        #pragma unroll
        for (int kb = 0; kb < 4; kb++) {
            #pragma unroll
            for (int j = 0; j < 8; j++) {
                uint32_t bf[2];
                ldsm_x2(bf, saddr(&Kc[8*j + rK][8*kb + wK]));
                mma_tf32(sa[j], qa[kb], bf[0], bf[1]);
            }
        }

        #pragma unroll
        for (int j = 0; j < 8; j++)
            #pragma unroll
            for (int r = 0; r < 4; r++) sa[j][r] *= scale;

        // online softmax (rows gid [A], gid+8 [B])
        float mxA = -1e30f, mxB = -1e30f;
        #pragma unroll
        for (int j = 0; j < 8; j++) {
            mxA = fmaxf(mxA, fmaxf(sa[j][0], sa[j][1]));
            mxB = fmaxf(mxB, fmaxf(sa[j][2], sa[j][3]));
        }
        #pragma unroll
        for (int o = 1; o <= 2; o <<= 1) {
            mxA = fmaxf(mxA, __shfl_xor_sync(0xffffffffu, mxA, o));
            mxB = fmaxf(mxB, __shfl_xor_sync(0xffffffffu, mxB, o));
        }
        const float mnA = fmaxf(mA, mxA);
        const float mnB = fmaxf(mB, mxB);
        const float corrA = __expf(mA - mnA);
        const float corrB = __expf(mB - mnB);
        mA = mnA; mB = mnB;

        float psumA = 0.f, psumB = 0.f;
        #pragma unroll
        for (int j = 0; j < 8; j++) {
            const float p0 = __expf(sa[j][0] - mA);
            const float p1 = __expf(sa[j][1] - mA);
            const float p2 = __expf(sa[j][2] - mB);
            const float p3 = __expf(sa[j][3] - mB);
            psumA += p0 + p1;
            psumB += p2 + p3;
            Pw[gid    ][8*j + 2*t]     = f2tf(p0);
            Pw[gid    ][8*j + 2*t + 1] = f2tf(p1);
            Pw[gid + 8][8*j + 2*t]     = f2tf(p2);
            Pw[gid + 8][8*j + 2*t + 1] = f2tf(p3);
        }
        lA = lA * corrA + psumA;
        lB = lB * corrB + psumB;
        #pragma unroll
        for (int j = 0; j < 4; j++) {
            oacc[j][0] *= corrA; oacc[j][1] *= corrA;
            oacc[j][2] *= corrB; oacc[j][3] *= corrB;
        }
        __syncwarp();

        // O += P V ; V natural layout (scalar b-frag reads, conflict-free)
        #pragma unroll
        for (int ks = 0; ks < 8; ks++) {
            uint32_t af[4];
            ldsm_x4(af, saddr(&Pw[rP][8*ks + wP]));
            #pragma unroll
            for (int j = 0; j < 4; j++) {
                const int dv = 8*j + gid;
                const uint32_t b0 = __float_as_uint(Vc[8*ks + t    ][dv]);
                const uint32_t b1 = __float_as_uint(Vc[8*ks + t + 4][dv]);
                mma_tf32(oacc[j], af, b0, b1);
            }
        }
    }

    #pragma unroll
    for (int o = 1; o <= 2; o <<= 1) {
        lA += __shfl_xor_sync(0xffffffffu, lA, o);
        lB += __shfl_xor_sync(0xffffffffu, lB, o);
    }
    const float invA = 1.0f / lA;
    const float invB = 1.0f / lB;

    #pragma unroll
    for (int j = 0; j < 4; j++) {
        const int gc = h*32 + 8*j + 2*t;
        const int rA2 = b*SEQ + qbase + qw + gid;
        const int rB2 = rA2 + 8;
        *(float2*)&out[(size_t)rA2 * DMODEL + gc] =
            make_float2(f2tf(oacc[j][0]*invA), f2tf(oacc[j][1]*invA));
        *(float2*)&out[(size_t)rB2 * DMODEL + gc] =
            make_float2(f2tf(oacc[j][2]*invB), f2tf(oacc[j][3]*invB));
    }
}

// ---------------- launch ------------------------------------------------------
extern "C" void kernel_launch(void* const* d_in, const int* in_sizes, int n_in,
                              void* d_out, int out_size)
{
    const float* x     = (const float*)d_in[0];
    const float* Wq    = (const float*)d_in[1];
    const float* Wk    = (const float*)d_in[2];
    const float* Wv    = (const float*)d_in[3];
    const float* Wo    = (const float*)d_in[4];
    const float* ln1_g = (const float*)d_in[5];
    const float* ln1_b = (const float*)d_in[6];
    const float* ln2_g = (const float*)d_in[7];
    const float* ln2_b = (const float*)d_in[8];
    const float* W2    = (const float*)d_in[9];
    const float* b2    = (const float*)d_in[10];
    const float* W3    = (const float*)d_in[11];
    const float* b3    = (const float*)d_in[12];
    float* out = (float*)d_out;

    float *xn, *qkv, *attn, *mlpin, *yn, *hbuf, *wr;
    cudaGetSymbolAddress((void**)&xn,    g_xn);
    cudaGetSymbolAddress((void**)&qkv,   g_qkv);
    cudaGetSymbolAddress((void**)&attn,  g_attn);
    cudaGetSymbolAddress((void**)&mlpin, g_mlpin);
    cudaGetSymbolAddress((void**)&yn,    g_yn);
    cudaGetSymbolAddress((void**)&hbuf,  g_h);
    cudaGetSymbolAddress((void**)&wr,    g_wr);

    const float* wr_q = wr;
    const float* wr_k = wr + WSMALL;
    const float* wr_v = wr + 2*WSMALL;
    const float* wr_o = wr + 3*WSMALL;
    const float* wr_2 = wr + 4*WSMALL;
    const float* wr_3 = wr + 4*WSMALL + WBIG;

    const int smGemm = 4*(64 + 128)*36*4;                              // 110592
    const int smAttn = (128*36 + 2*64*36 + 2*64*40 + 8*16*68) * 4;     // 92160

    cudaFuncSetAttribute(gemm_v3<EPI_QKV>,        cudaFuncAttributeMaxDynamicSharedMemorySize, smGemm);
    cudaFuncSetAttribute(gemm_v3<EPI_BIAS_GELU>,  cudaFuncAttributeMaxDynamicSharedMemorySize, smGemm);
    cudaFuncSetAttribute(gemm_v3<EPI_RESID>,      cudaFuncAttributeMaxDynamicSharedMemorySize, smGemm);
    cudaFuncSetAttribute(gemm_v3<EPI_BIAS_RESID>, cudaFuncAttributeMaxDynamicSharedMemorySize, smGemm);
    cudaFuncSetAttribute(flash_attn_v3,           cudaFuncAttributeMaxDynamicSharedMemorySize, smAttn);

    // weight rounding (runs every call; deterministic, ~3MB traffic)
    round_weights<<<(4*WSMALL + 2*WBIG)/4/256, 256>>>(Wq, Wk, Wv, Wo, W2, W3, wr);

    // LN1 (tf32-rounded output)
    ln_kernel<<<NROW, 256>>>(x, ln1_g, ln1_b, xn);

    // Fused QKV projections (RoPE on Q,K cols), rounded outputs
    gemm_v3<EPI_QKV><<<dim3(6, NROW/64), 256, smGemm>>>(
        xn, DMODEL, wr_q, DMODEL, qkv, 768, DMODEL, wr_k, wr_v, 0);

    // attention (rounded output)
    flash_attn_v3<<<dim3(SEQ/128, BATCH*NHEAD), 256, smAttn>>>(qkv, attn);

    // output projection + residual -> mlp_in (fp32)
    gemm_v3<EPI_RESID><<<dim3(2, NROW/64), 256, smGemm>>>(
        attn, DMODEL, wr_o, DMODEL, mlpin, DMODEL, DMODEL, nullptr, x, DMODEL);

    // LN2 (rounded output)
    ln_kernel<<<NROW, 256>>>(mlpin, ln2_g, ln2_b, yn);

    // MLP
    gemm_v3<EPI_BIAS_GELU><<<dim3(8, NROW/64), 256, smGemm>>>(
        yn, DMODEL, wr_2, DMODEL, hbuf, DMLP, DMODEL, b2, nullptr, 0);
    gemm_v3<EPI_BIAS_RESID><<<dim3(2, NROW/64), 256, smGemm>>>(
        hbuf, DMLP, wr_3, DMLP, out, DMODEL, DMLP, b3, mlpin, DMODEL);
}

// round 8
// speedup vs baseline: 1.0304x; 1.0304x over previous
#include <cuda_runtime.h>
#include <math.h>
#include <stdint.h>

#define BATCH 2
#define SEQ   4096
#define DMODEL 256
#define NHEAD 8
#define DHEAD 32
#define DMLP  1024
#define NROW  (BATCH*SEQ)   // 8192

// ---------------- scratch (static device globals; no allocation) -------------
__device__ float g_xn[NROW*DMODEL];
__device__ float g_qkv[NROW*3*DMODEL];
__device__ float g_vt[BATCH*NHEAD*DHEAD*SEQ];   // V transposed: [b][h][d][s]
__device__ float g_attn[NROW*DMODEL];
__device__ float g_mlpin[NROW*DMODEL];
__device__ float g_yn[NROW*DMODEL];
__device__ float g_h[NROW*DMLP];
#define WSMALL (DMODEL*DMODEL)        // 65536
#define WBIG   (DMLP*DMODEL)          // 262144
__device__ float g_wr[4*WSMALL + 2*WBIG];   // rounded weights

// inv_freq[i] = 10000^(-i/16) = 10^(-i/4)
__constant__ float c_invfreq[16] = {
    1.0f, 0.5623413251903491f, 0.31622776601683794f, 0.17782794100389228f,
    0.1f, 0.05623413251903491f, 0.031622776601683794f, 0.017782794100389228f,
    0.01f, 0.005623413251903491f, 0.0031622776601683794f, 0.0017782794100389228f,
    0.001f, 0.0005623413251903491f, 0.00031622776601683794f, 0.00017782794100389227f
};

// (1/sqrt(32)) * log2(e): folded into Q so softmax runs in log2 domain
#define QSCALE 0.2550348754541408f

__device__ __forceinline__ float f2tf(float x) {
    uint32_t u;
    asm("cvt.rna.tf32.f32 %0, %1;" : "=r"(u) : "f"(x));
    return __uint_as_float(u);
}
__device__ __forceinline__ float ex2(float x) {
    float y;
    asm("ex2.approx.f32 %0, %1;" : "=f"(y) : "f"(x));
    return y;
}
__device__ __forceinline__ void cp16(float* smem_dst, const float* gmem_src) {
    uint32_t s = (uint32_t)__cvta_generic_to_shared(smem_dst);
    asm volatile("cp.async.cg.shared.global [%0], [%1], 16;" :: "r"(s), "l"(gmem_src));
}
#define CP_COMMIT() asm volatile("cp.async.commit_group;")
__device__ __forceinline__ uint32_t saddr(const void* p) {
    return (uint32_t)__cvta_generic_to_shared(p);
}
__device__ __forceinline__ void ldsm_x4(uint32_t* r, uint32_t a) {
    asm volatile("ldmatrix.sync.aligned.m8n8.x4.shared.b16 {%0,%1,%2,%3}, [%4];"
        : "=r"(r[0]), "=r"(r[1]), "=r"(r[2]), "=r"(r[3]) : "r"(a));
}
__device__ __forceinline__ void ldsm_x2(uint32_t* r, uint32_t a) {
    asm volatile("ldmatrix.sync.aligned.m8n8.x2.shared.b16 {%0,%1}, [%2];"
        : "=r"(r[0]), "=r"(r[1]) : "r"(a));
}
__device__ __forceinline__ void mma_tf32(float* d, const uint32_t* a, uint32_t b0, uint32_t b1) {
    asm volatile("mma.sync.aligned.m16n8k8.row.col.f32.tf32.tf32.f32 "
        "{%0,%1,%2,%3}, {%4,%5,%6,%7}, {%8,%9}, {%0,%1,%2,%3};\n"
        : "+f"(d[0]), "+f"(d[1]), "+f"(d[2]), "+f"(d[3])
        : "r"(a[0]), "r"(a[1]), "r"(a[2]), "r"(a[3]), "r"(b0), "r"(b1));
}

// ---------------- weight pre-rounding (rna -> tf32-exact fp32) ----------------
__global__ void round_weights(const float* __restrict__ Wq, const float* __restrict__ Wk,
                              const float* __restrict__ Wv, const float* __restrict__ Wo,
                              const float* __restrict__ W2, const float* __restrict__ W3,
                              float* __restrict__ out)
{
    const int i = blockIdx.x * blockDim.x + threadIdx.x;   // float4 index
    const int n1 = WSMALL / 4;
    const float4* src;
    int local;
    if (i < 4*n1) {
        const float* w4[4] = {Wq, Wk, Wv, Wo};
        src = (const float4*)w4[i / n1];
        local = i % n1;
    } else if (i < 4*n1 + WBIG/4) {
        src = (const float4*)W2; local = i - 4*n1;
    } else {
        src = (const float4*)W3; local = i - 4*n1 - WBIG/4;
    }
    float4 v = src[local];
    v.x = f2tf(v.x); v.y = f2tf(v.y); v.z = f2tf(v.z); v.w = f2tf(v.w);
    ((float4*)out)[i] = v;
}

// ---------------- LayerNorm: one block per row, rounded output ---------------
__global__ void ln_kernel(const float* __restrict__ x, const float* __restrict__ g,
                          const float* __restrict__ b, float* __restrict__ out)
{
    const int row = blockIdx.x;
    const int t   = threadIdx.x;
    const float v = x[row*DMODEL + t];
    __shared__ float red1[8];
    __shared__ float red2[8];

    float s = v;
    #pragma unroll
    for (int o = 16; o > 0; o >>= 1) s += __shfl_xor_sync(0xffffffffu, s, o);
    if ((t & 31) == 0) red1[t >> 5] = s;
    __syncthreads();
    float mean = 0.f;
    #pragma unroll
    for (int i = 0; i < 8; i++) mean += red1[i];
    mean *= (1.0f/DMODEL);
    const float d = v - mean;

    float s2 = d*d;
    #pragma unroll
    for (int o = 16; o > 0; o >>= 1) s2 += __shfl_xor_sync(0xffffffffu, s2, o);
    if ((t & 31) == 0) red2[t >> 5] = s2;
    __syncthreads();
    float var = 0.f;
    #pragma unroll
    for (int i = 0; i < 8; i++) var += red2[i];
    var *= (1.0f/DMODEL);

    out[row*DMODEL + t] = f2tf(d * rsqrtf(var + 1e-5f) * g[t] + b[t]);
}

// ---------------- GEMM (C = A * B^T), tf32 mma, 4-stage cp.async, ldmatrix ---
// Tile 64x128x32, 256 thr, 8 warps 2(m)x4(n), warp 32x32.
enum { EPI_NONE=0, EPI_ROPE=1, EPI_BIAS_GELU=2, EPI_RESID=3, EPI_BIAS_RESID=4, EPI_QKV=5 };

template<int EPI>
__global__ __launch_bounds__(256, 2)
void gemm_v3(const float* __restrict__ A, int lda,
             const float* __restrict__ Bw, int ldb,
             float* __restrict__ C, int ldc, int K,
             const float* __restrict__ bias,
             const float* __restrict__ resid, int ldr,
             float* __restrict__ vt)
{
    extern __shared__ float sm[];
    float (*As)[36] = (float(*)[36])sm;               // [4*64][36]
    float (*Bs)[36] = (float(*)[36])(sm + 4*64*36);   // [4*128][36]

    const int tid = threadIdx.x;
    const int w = tid>>5, L = tid&31, gid = L>>2, t = L&3;
    const int wm = w>>2, wn = w&3;
    const int m0 = blockIdx.y * 64;
    const int bx = blockIdx.x;

    const float* Bmat;
    int nlocal0, ncout0;
    if (EPI == EPI_QKV) {
        Bmat = (bx < 2) ? Bw : (bx < 4) ? bias : resid;
        nlocal0 = (bx & 1) * 128;
        ncout0  = bx * 128;
    } else {
        Bmat = Bw;
        nlocal0 = bx * 128;
        ncout0  = nlocal0;
    }

    float acc[2][4][4];
    #pragma unroll
    for (int i = 0; i < 2; i++)
        #pragma unroll
        for (int j = 0; j < 4; j++)
            #pragma unroll
            for (int r = 0; r < 4; r++) acc[i][j][r] = 0.f;

    auto loadA = [&](int stg, int k0) {
        #pragma unroll
        for (int c = 0; c < 2; c++) {
            const int ci = tid*2 + c;
            const int r = ci>>3, cc = (ci&7)*4;
            cp16(&As[stg*64 + r][cc], A + (size_t)(m0+r)*lda + k0 + cc);
        }
    };
    auto loadB = [&](int stg, int k0) {
        #pragma unroll
        for (int c = 0; c < 4; c++) {
            const int ci = tid*4 + c;
            const int r = ci>>3, cc = (ci&7)*4;
            cp16(&Bs[stg*128 + r][cc], Bmat + (size_t)(nlocal0+r)*ldb + k0 + cc);
        }
    };

    loadA(0, 0);  loadB(0, 0);  CP_COMMIT();
    loadA(1, 32); loadB(1, 32); CP_COMMIT();
    loadA(2, 64); loadB(2, 64); CP_COMMIT();

    // ldmatrix lane addressing
    const int rA = (L&7) + ((L>>3)&1)*8;
    const int wA = (L>>4)*4;
    const int rB = (L&7);
    const int wB = ((L>>3)&1)*4;

    const int iters = K/32;
    for (int it = 0; it < iters; it++) {
        asm volatile("cp.async.wait_group 2;");
        __syncthreads();

        const float (*Ac)[36] = (const float(*)[36])(As + (it&3)*64);
        const float (*Bc)[36] = (const float(*)[36])(Bs + (it&3)*128);

        #pragma unroll
        for (int kb = 0; kb < 4; kb++) {
            uint32_t af[2][4];
            #pragma unroll
            for (int mi = 0; mi < 2; mi++)
                ldsm_x4(af[mi], saddr(&Ac[wm*32 + mi*16 + rA][8*kb + wA]));
            #pragma unroll
            for (int nj = 0; nj < 4; nj++) {
                uint32_t bf[2];
                ldsm_x2(bf, saddr(&Bc[wn*32 + nj*8 + rB][8*kb + wB]));
                mma_tf32(acc[0][nj], af[0], bf[0], bf[1]);
                mma_tf32(acc[1][nj], af[1], bf[0], bf[1]);
            }
        }

        if (it + 3 < iters) {
            loadA((it+3)&3, (it+3)*32);
            loadB((it+3)&3, (it+3)*32);
            CP_COMMIT();
        }
    }

    // epilogue
    #pragma unroll
    for (int mi = 0; mi < 2; mi++) {
        #pragma unroll
        for (int half = 0; half < 2; half++) {
            const int gm = m0 + wm*32 + mi*16 + gid + half*8;
            #pragma unroll
            for (int nj = 0; nj < 4; nj++) {
                const int gc = ncout0 + wn*32 + nj*8 + 2*t;   // even
                float v0 = acc[mi][nj][half*2 + 0];
                float v1 = acc[mi][nj][half*2 + 1];

                if (EPI == EPI_QKV) {
                    if (ncout0 < 512) {
                        // Q or K: rope; Q additionally folds scale*log2e
                        const int s  = gm & (SEQ - 1);
                        const int dd = gc & (DHEAD - 1);
                        const float ang = (float)s * c_invfreq[dd >> 1];
                        float sn, cs;
                        sincosf(ang, &sn, &cs);
                        const float e = v0, o = v1;
                        v0 = e*cs - o*sn;
                        v1 = o*cs + e*sn;
                        if (ncout0 < 256) { v0 *= QSCALE; v1 *= QSCALE; }
                        v0 = f2tf(v0); v1 = f2tf(v1);
                        *(float2*)&C[(size_t)gm * ldc + gc] = make_float2(v0, v1);
                    } else {
                        // V: scatter transposed into vt[b][h][d][s]
                        v0 = f2tf(v0); v1 = f2tf(v1);
                        const int gc512 = gc - 512;
                        const int hh = gc512 >> 5, dd = gc512 & 31;
                        const size_t vb = (((size_t)(gm >> 12) * NHEAD + hh) * DHEAD + dd) * SEQ
                                          + (gm & (SEQ - 1));
                        vt[vb]       = v0;
                        vt[vb + SEQ] = v1;
                    }
                } else {
                    if (EPI == EPI_BIAS_GELU) {
                        float t0 = v0 + bias[gc], t1 = v1 + bias[gc + 1];
                        v0 = f2tf(0.5f * t0 * (1.0f + erff(t0 * 0.7071067811865476f)));
                        v1 = f2tf(0.5f * t1 * (1.0f + erff(t1 * 0.7071067811865476f)));
                    } else if (EPI == EPI_RESID) {
                        v0 += resid[(size_t)gm * ldr + gc];      // mlpin stays fp32
                        v1 += resid[(size_t)gm * ldr + gc + 1];
                    } else if (EPI == EPI_BIAS_RESID) {
                        v0 += bias[gc]     + resid[(size_t)gm * ldr + gc];
                        v1 += bias[gc + 1] + resid[(size_t)gm * ldr + gc + 1];
                    }
                    *(float2*)&C[(size_t)gm * ldc + gc] = make_float2(v0, v1);
                }
            }
        }
    }
}

// ---------------- Flash attention, tf32 mma + ldmatrix everywhere ------------
// CTA: 128 q-rows, 8 warps (each 16 q-rows x 64 k-cols). K-tile = 64, 3 stages.
// Q carries scale*log2e; softmax in log2 domain (ex2).
__global__ __launch_bounds__(256, 2)
void flash_attn_v4(const float* __restrict__ qkv, const float* __restrict__ vt,
                   float* __restrict__ out)
{
    extern __shared__ float sm[];
    float (*Qs)[36]  = (float(*)[36])sm;                                  // [128][36]
    float (*Ks)[36]  = (float(*)[36])(sm + 128*36);                       // [3*64][36]
    float (*Vts)[68] = (float(*)[68])(sm + 128*36 + 3*64*36);             // [3*32][68]
    float (*PsA)[68] = (float(*)[68])(sm + 128*36 + 3*64*36 + 3*32*68);   // [8*16][68]

    const int tid = threadIdx.x;
    const int w = tid>>5, L = tid&31, gid = L>>2, t = L&3;
    const int b = blockIdx.y >> 3, h = blockIdx.y & 7;
    const int qbase = blockIdx.x * 128;
    const int qw = w * 16;
    float (*Pw)[68] = PsA + w*16;

    const size_t qoff  = (size_t)(b*SEQ + qbase) * 768 + h*32;
    const size_t kvoff = (size_t)(b*SEQ) * 768 + h*32;
    const float* vtg   = vt + (size_t)(b*NHEAD + h) * DHEAD * SEQ;

    #pragma unroll
    for (int c = 0; c < 4; c++) {
        const int ci = tid*4 + c;
        const int r = ci>>3, cc = (ci&7)*4;
        cp16(&Qs[r][cc], qkv + qoff + (size_t)r*768 + cc);
    }
    auto loadKV = [&](int stg, int kt) {
        const int kbase = kt*64;
        #pragma unroll
        for (int c = 0; c < 2; c++) {
            const int ci = tid*2 + c;
            const int r = ci>>3, cc = (ci&7)*4;       // K: 64 rows x 8 chunks
            cp16(&Ks[stg*64 + r][cc], qkv + kvoff + (size_t)(kbase + r)*768 + 256 + cc);
        }
        #pragma unroll
        for (int c = 0; c < 2; c++) {
            const int ci = tid*2 + c;
            const int d = ci>>4, cc = (ci&15)*4;      // Vt: 32 rows x 16 chunks
            cp16(&Vts[stg*32 + d][cc], vtg + (size_t)d*SEQ + kbase + cc);
        }
    };
    loadKV(0, 0); CP_COMMIT();
    loadKV(1, 1); CP_COMMIT();
    asm volatile("cp.async.wait_group 1;");
    __syncthreads();

    uint32_t qa[4][4];
    #pragma unroll
    for (int kb = 0; kb < 4; kb++) {
        qa[kb][0] = __float_as_uint(Qs[qw + gid    ][8*kb + t]);
        qa[kb][1] = __float_as_uint(Qs[qw + gid + 8][8*kb + t]);
        qa[kb][2] = __float_as_uint(Qs[qw + gid    ][8*kb + t + 4]);
        qa[kb][3] = __float_as_uint(Qs[qw + gid + 8][8*kb + t + 4]);
    }

    // ldmatrix lane addressing
    const int rK = (L&7);
    const int wK = ((L>>3)&1)*4;
    const int rP = (L&7) + ((L>>3)&1)*8;
    const int wP = (L>>4)*4;

    float oacc[4][4];
    #pragma unroll
    for (int j = 0; j < 4; j++)
        #pragma unroll
        for (int r = 0; r < 4; r++) oacc[j][r] = 0.f;
    float mA = -1e30f, mB = -1e30f, lA = 0.f, lB = 0.f;

    for (int kt = 0; kt < SEQ/64; kt++) {
        if (kt > 0) { asm volatile("cp.async.wait_group 1;"); }
        __syncthreads();
        if (kt + 2 < SEQ/64) { loadKV((kt+2)%3, kt+2); CP_COMMIT(); }

        const int stg = kt % 3;
        const float (*Kc)[36]  = (const float(*)[36])(Ks + stg*64);
        const float (*Vc)[68]  = (const float(*)[68])(Vts + stg*32);

        // S' = (Q*scale*log2e) K^T
        float sa[8][4];
        #pragma unroll
        for (int j = 0; j < 8; j++)
            #pragma unroll
            for (int r = 0; r < 4; r++) sa[j][r] = 0.f;

        #pragma unroll
        for (int kb = 0; kb < 4; kb++) {
            #pragma unroll
            for (int j = 0; j < 8; j++) {
                uint32_t bf[2];
                ldsm_x2(bf, saddr(&Kc[8*j + rK][8*kb + wK]));
                mma_tf32(sa[j], qa[kb], bf[0], bf[1]);
            }
        }

        // online softmax in log2 domain (rows gid [A], gid+8 [B])
        float mxA = -1e30f, mxB = -1e30f;
        #pragma unroll
        for (int j = 0; j < 8; j++) {
            mxA = fmaxf(mxA, fmaxf(sa[j][0], sa[j][1]));
            mxB = fmaxf(mxB, fmaxf(sa[j][2], sa[j][3]));
        }
        #pragma unroll
        for (int o = 1; o <= 2; o <<= 1) {
            mxA = fmaxf(mxA, __shfl_xor_sync(0xffffffffu, mxA, o));
            mxB = fmaxf(mxB, __shfl_xor_sync(0xffffffffu, mxB, o));
        }
        const float mnA = fmaxf(mA, mxA);
        const float mnB = fmaxf(mB, mxB);
        const float corrA = ex2(mA - mnA);
        const float corrB = ex2(mB - mnB);
        mA = mnA; mB = mnB;

        float psumA = 0.f, psumB = 0.f;
        #pragma unroll
        for (int j = 0; j < 8; j++) {
            const float p0 = ex2(sa[j][0] - mA);
            const float p1 = ex2(sa[j][1] - mA);
            const float p2 = ex2(sa[j][2] - mB);
            const float p3 = ex2(sa[j][3] - mB);
            psumA += p0 + p1;
            psumB += p2 + p3;
            Pw[gid    ][8*j + 2*t]     = f2tf(p0);
            Pw[gid    ][8*j + 2*t + 1] = f2tf(p1);
            Pw[gid + 8][8*j + 2*t]     = f2tf(p2);
            Pw[gid + 8][8*j + 2*t + 1] = f2tf(p3);
        }
        lA = lA * corrA + psumA;
        lB = lB * corrB + psumB;
        #pragma unroll
        for (int j = 0; j < 4; j++) {
            oacc[j][0] *= corrA; oacc[j][1] *= corrA;
            oacc[j][2] *= corrB; oacc[j][3] *= corrB;
        }
        __syncwarp();

        // O += P V ; Vt transposed layout -> ldmatrix b-frags
        #pragma unroll
        for (int ks = 0; ks < 8; ks++) {
            uint32_t af[4];
            ldsm_x4(af, saddr(&Pw[rP][8*ks + wP]));
            #pragma unroll
            for (int j = 0; j < 4; j++) {
                uint32_t bf[2];
                ldsm_x2(bf, saddr(&Vc[8*j + rK][8*ks + wK]));
                mma_tf32(oacc[j], af, bf[0], bf[1]);
            }
        }
    }

    #pragma unroll
    for (int o = 1; o <= 2; o <<= 1) {
        lA += __shfl_xor_sync(0xffffffffu, lA, o);
        lB += __shfl_xor_sync(0xffffffffu, lB, o);
    }
    const float invA = 1.0f / lA;
    const float invB = 1.0f / lB;

    #pragma unroll
    for (int j = 0; j < 4; j++) {
        const int gc = h*32 + 8*j + 2*t;
        const int rA2 = b*SEQ + qbase + qw + gid;
        const int rB2 = rA2 + 8;
        *(float2*)&out[(size_t)rA2 * DMODEL + gc] =
            make_float2(f2tf(oacc[j][0]*invA), f2tf(oacc[j][1]*invA));
        *(float2*)&out[(size_t)rB2 * DMODEL + gc] =
            make_float2(f2tf(oacc[j][2]*invB), f2tf(oacc[j][3]*invB));
    }
}

// ---------------- launch ------------------------------------------------------
extern "C" void kernel_launch(void* const* d_in, const int* in_sizes, int n_in,
                              void* d_out, int out_size)
{
    const float* x     = (const float*)d_in[0];
    const float* Wq    = (const float*)d_in[1];
    const float* Wk    = (const float*)d_in[2];
    const float* Wv    = (const float*)d_in[3];
    const float* Wo    = (const float*)d_in[4];
    const float* ln1_g = (const float*)d_in[5];
    const float* ln1_b = (const float*)d_in[6];
    const float* ln2_g = (const float*)d_in[7];
    const float* ln2_b = (const float*)d_in[8];
    const float* W2    = (const float*)d_in[9];
    const float* b2    = (const float*)d_in[10];
    const float* W3    = (const float*)d_in[11];
    const float* b3    = (const float*)d_in[12];
    float* out = (float*)d_out;

    float *xn, *qkv, *vt, *attn, *mlpin, *yn, *hbuf, *wr;
    cudaGetSymbolAddress((void**)&xn,    g_xn);
    cudaGetSymbolAddress((void**)&qkv,   g_qkv);
    cudaGetSymbolAddress((void**)&vt,    g_vt);
    cudaGetSymbolAddress((void**)&attn,  g_attn);
    cudaGetSymbolAddress((void**)&mlpin, g_mlpin);
    cudaGetSymbolAddress((void**)&yn,    g_yn);
    cudaGetSymbolAddress((void**)&hbuf,  g_h);
    cudaGetSymbolAddress((void**)&wr,    g_wr);

    const float* wr_q = wr;
    const float* wr_k = wr + WSMALL;
    const float* wr_v = wr + 2*WSMALL;
    const float* wr_o = wr + 3*WSMALL;
    const float* wr_2 = wr + 4*WSMALL;
    const float* wr_3 = wr + 4*WSMALL + WBIG;

    const int smGemm = 4*(64 + 128)*36*4;                                  // 110592
    const int smAttn = (128*36 + 3*64*36 + 3*32*68 + 8*16*68) * 4;         // 107008

    cudaFuncSetAttribute(gemm_v3<EPI_QKV>,        cudaFuncAttributeMaxDynamicSharedMemorySize, smGemm);
    cudaFuncSetAttribute(gemm_v3<EPI_BIAS_GELU>,  cudaFuncAttributeMaxDynamicSharedMemorySize, smGemm);
    cudaFuncSetAttribute(gemm_v3<EPI_RESID>,      cudaFuncAttributeMaxDynamicSharedMemorySize, smGemm);
    cudaFuncSetAttribute(gemm_v3<EPI_BIAS_RESID>, cudaFuncAttributeMaxDynamicSharedMemorySize, smGemm);
    cudaFuncSetAttribute(flash_attn_v4,           cudaFuncAttributeMaxDynamicSharedMemorySize, smAttn);

    // weight rounding (deterministic, ~3MB traffic)
    round_weights<<<(4*WSMALL + 2*WBIG)/4/256, 256>>>(Wq, Wk, Wv, Wo, W2, W3, wr);

    // LN1 (tf32-rounded output)
    ln_kernel<<<NROW, 256>>>(x, ln1_g, ln1_b, xn);

    // Fused QKV projections: Q (rope + scale*log2e), K (rope), V -> transposed vt
    gemm_v3<EPI_QKV><<<dim3(6, NROW/64), 256, smGemm>>>(
        xn, DMODEL, wr_q, DMODEL, qkv, 768, DMODEL, wr_k, wr_v, 0, vt);

    // attention
    flash_attn_v4<<<dim3(SEQ/128, BATCH*NHEAD), 256, smAttn>>>(qkv, vt, attn);

    // output projection + residual -> mlp_in (fp32)
    gemm_v3<EPI_RESID><<<dim3(2, NROW/64), 256, smGemm>>>(
        attn, DMODEL, wr_o, DMODEL, mlpin, DMODEL, DMODEL, nullptr, x, DMODEL, nullptr);

    // LN2 (rounded output)
    ln_kernel<<<NROW, 256>>>(mlpin, ln2_g, ln2_b, yn);

    // MLP
    gemm_v3<EPI_BIAS_GELU><<<dim3(8, NROW/64), 256, smGemm>>>(
        yn, DMODEL, wr_2, DMODEL, hbuf, DMLP, DMODEL, b2, nullptr, 0, nullptr);
    gemm_v3<EPI_BIAS_RESID><<<dim3(2, NROW/64), 256, smGemm>>>(
        hbuf, DMLP, wr_3, DMLP, out, DMODEL, DMLP, b3, mlpin, DMODEL, nullptr);
}

// round 10
// speedup vs baseline: 1.3451x; 1.3055x over previous
#include <cuda_runtime.h>
#include <cuda_bf16.h>
#include <math.h>
#include <stdint.h>

#define BATCH 2
#define SEQ   4096
#define DMODEL 256
#define NHEAD 8
#define DHEAD 32
#define DMLP  1024
#define NROW  (BATCH*SEQ)   // 8192

// ---------------- scratch (static device globals; no allocation) -------------
__device__ float g_xn[NROW*DMODEL];
__device__ float g_qkv[NROW*3*DMODEL];
__device__ __nv_bfloat16 g_vt[BATCH*NHEAD*DHEAD*SEQ];   // V^T bf16: [b][h][d][s]
__device__ float g_attn[NROW*DMODEL];
__device__ float g_mlpin[NROW*DMODEL];
__device__ float g_yn[NROW*DMODEL];
__device__ float g_h[NROW*DMLP];
#define WSMALL (DMODEL*DMODEL)        // 65536
#define WBIG   (DMLP*DMODEL)          // 262144
__device__ float g_wr[4*WSMALL + 2*WBIG];   // rounded weights

// inv_freq[i] = 10000^(-i/16) = 10^(-i/4)
__constant__ float c_invfreq[16] = {
    1.0f, 0.5623413251903491f, 0.31622776601683794f, 0.17782794100389228f,
    0.1f, 0.05623413251903491f, 0.031622776601683794f, 0.017782794100389228f,
    0.01f, 0.005623413251903491f, 0.0031622776601683794f, 0.0017782794100389228f,
    0.001f, 0.0005623413251903491f, 0.00031622776601683794f, 0.00017782794100389227f
};

// (1/sqrt(32)) * log2(e): folded into Q so softmax runs in log2 domain
#define QSCALE 0.2550348754541408f

__device__ __forceinline__ float f2tf(float x) {
    uint32_t u;
    asm("cvt.rna.tf32.f32 %0, %1;" : "=r"(u) : "f"(x));
    return __uint_as_float(u);
}
__device__ __forceinline__ float ex2(float x) {
    float y;
    asm("ex2.approx.f32 %0, %1;" : "=f"(y) : "f"(x));
    return y;
}
// pack two fp32 -> bf16x2 (lo = first k, hi = second k)
__device__ __forceinline__ uint32_t pack_bf16(float lo, float hi) {
    uint32_t r;
    asm("cvt.rn.bf16x2.f32 %0, %1, %2;" : "=r"(r) : "f"(hi), "f"(lo));
    return r;
}
__device__ __forceinline__ void cp16(void* smem_dst, const void* gmem_src) {
    uint32_t s = (uint32_t)__cvta_generic_to_shared(smem_dst);
    asm volatile("cp.async.cg.shared.global [%0], [%1], 16;" :: "r"(s), "l"(gmem_src));
}
#define CP_COMMIT() asm volatile("cp.async.commit_group;")
__device__ __forceinline__ uint32_t saddr(const void* p) {
    return (uint32_t)__cvta_generic_to_shared(p);
}
__device__ __forceinline__ void ldsm_x4(uint32_t* r, uint32_t a) {
    asm volatile("ldmatrix.sync.aligned.m8n8.x4.shared.b16 {%0,%1,%2,%3}, [%4];"
        : "=r"(r[0]), "=r"(r[1]), "=r"(r[2]), "=r"(r[3]) : "r"(a));
}
__device__ __forceinline__ void ldsm_x2(uint32_t* r, uint32_t a) {
    asm volatile("ldmatrix.sync.aligned.m8n8.x2.shared.b16 {%0,%1}, [%2];"
        : "=r"(r[0]), "=r"(r[1]) : "r"(a));
}
__device__ __forceinline__ void mma_tf32(float* d, const uint32_t* a, uint32_t b0, uint32_t b1) {
    asm volatile("mma.sync.aligned.m16n8k8.row.col.f32.tf32.tf32.f32 "
        "{%0,%1,%2,%3}, {%4,%5,%6,%7}, {%8,%9}, {%0,%1,%2,%3};\n"
        : "+f"(d[0]), "+f"(d[1]), "+f"(d[2]), "+f"(d[3])
        : "r"(a[0]), "r"(a[1]), "r"(a[2]), "r"(a[3]), "r"(b0), "r"(b1));
}
__device__ __forceinline__ void mma_bf16(float* d, const uint32_t* a, uint32_t b0, uint32_t b1) {
    asm volatile("mma.sync.aligned.m16n8k16.row.col.f32.bf16.bf16.f32 "
        "{%0,%1,%2,%3}, {%4,%5,%6,%7}, {%8,%9}, {%0,%1,%2,%3};\n"
        : "+f"(d[0]), "+f"(d[1]), "+f"(d[2]), "+f"(d[3])
        : "r"(a[0]), "r"(a[1]), "r"(a[2]), "r"(a[3]), "r"(b0), "r"(b1));
}

// ---------------- weight pre-rounding (rna -> tf32-exact fp32) ----------------
__global__ void round_weights(const float* __restrict__ Wq, const float* __restrict__ Wk,
                              const float* __restrict__ Wv, const float* __restrict__ Wo,
                              const float* __restrict__ W2, const float* __restrict__ W3,
                              float* __restrict__ out)
{
    const int i = blockIdx.x * blockDim.x + threadIdx.x;   // float4 index
    const int n1 = WSMALL / 4;
    const float4* src;
    int local;
    if (i < 4*n1) {
        const float* w4[4] = {Wq, Wk, Wv, Wo};
        src = (const float4*)w4[i / n1];
        local = i % n1;
    } else if (i < 4*n1 + WBIG/4) {
        src = (const float4*)W2; local = i - 4*n1;
    } else {
        src = (const float4*)W3; local = i - 4*n1 - WBIG/4;
    }
    float4 v = src[local];
    v.x = f2tf(v.x); v.y = f2tf(v.y); v.z = f2tf(v.z); v.w = f2tf(v.w);
    ((float4*)out)[i] = v;
}

// ---------------- LayerNorm: one block per row, rounded output ---------------
__global__ void ln_kernel(const float* __restrict__ x, const float* __restrict__ g,
                          const float* __restrict__ b, float* __restrict__ out)
{
    const int row = blockIdx.x;
    const int t   = threadIdx.x;
    const float v = x[row*DMODEL + t];
    __shared__ float red1[8];
    __shared__ float red2[8];

    float s = v;
    #pragma unroll
    for (int o = 16; o > 0; o >>= 1) s += __shfl_xor_sync(0xffffffffu, s, o);
    if ((t & 31) == 0) red1[t >> 5] = s;
    __syncthreads();
    float mean = 0.f;
    #pragma unroll
    for (int i = 0; i < 8; i++) mean += red1[i];
    mean *= (1.0f/DMODEL);
    const float d = v - mean;

    float s2 = d*d;
    #pragma unroll
    for (int o = 16; o > 0; o >>= 1) s2 += __shfl_xor_sync(0xffffffffu, s2, o);
    if ((t & 31) == 0) red2[t >> 5] = s2;
    __syncthreads();
    float var = 0.f;
    #pragma unroll
    for (int i = 0; i < 8; i++) var += red2[i];
    var *= (1.0f/DMODEL);

    out[row*DMODEL + t] = f2tf(d * rsqrtf(var + 1e-5f) * g[t] + b[t]);
}

// ---------------- GEMM (C = A * B^T), tf32 mma, 4-stage cp.async, ldmatrix ---
// Tile 64x128x32, 256 thr, 8 warps 2(m)x4(n), warp 32x32.
enum { EPI_NONE=0, EPI_ROPE=1, EPI_BIAS_GELU=2, EPI_RESID=3, EPI_BIAS_RESID=4, EPI_QKV=5 };

template<int EPI>
__global__ __launch_bounds__(256, 2)
void gemm_v3(const float* __restrict__ A, int lda,
             const float* __restrict__ Bw, int ldb,
             float* __restrict__ C, int ldc, int K,
             const float* __restrict__ bias,
             const float* __restrict__ resid, int ldr,
             __nv_bfloat16* __restrict__ vt)
{
    extern __shared__ float sm[];
    float (*As)[36] = (float(*)[36])sm;               // [4*64][36]
    float (*Bs)[36] = (float(*)[36])(sm + 4*64*36);   // [4*128][36]

    const int tid = threadIdx.x;
    const int w = tid>>5, L = tid&31, gid = L>>2, t = L&3;
    const int wm = w>>2, wn = w&3;
    const int m0 = blockIdx.y * 64;
    const int bx = blockIdx.x;

    const float* Bmat;
    int nlocal0, ncout0;
    if (EPI == EPI_QKV) {
        Bmat = (bx < 2) ? Bw : (bx < 4) ? bias : resid;
        nlocal0 = (bx & 1) * 128;
        ncout0  = bx * 128;
    } else {
        Bmat = Bw;
        nlocal0 = bx * 128;
        ncout0  = nlocal0;
    }

    float acc[2][4][4];
    #pragma unroll
    for (int i = 0; i < 2; i++)
        #pragma unroll
        for (int j = 0; j < 4; j++)
            #pragma unroll
            for (int r = 0; r < 4; r++) acc[i][j][r] = 0.f;

    auto loadA = [&](int stg, int k0) {
        #pragma unroll
        for (int c = 0; c < 2; c++) {
            const int ci = tid*2 + c;
            const int r = ci>>3, cc = (ci&7)*4;
            cp16(&As[stg*64 + r][cc], A + (size_t)(m0+r)*lda + k0 + cc);
        }
    };
    auto loadB = [&](int stg, int k0) {
        #pragma unroll
        for (int c = 0; c < 4; c++) {
            const int ci = tid*4 + c;
            const int r = ci>>3, cc = (ci&7)*4;
            cp16(&Bs[stg*128 + r][cc], Bmat + (size_t)(nlocal0+r)*ldb + k0 + cc);
        }
    };

    loadA(0, 0);  loadB(0, 0);  CP_COMMIT();
    loadA(1, 32); loadB(1, 32); CP_COMMIT();
    loadA(2, 64); loadB(2, 64); CP_COMMIT();

    // ldmatrix lane addressing
    const int rA = (L&7) + ((L>>3)&1)*8;
    const int wA = (L>>4)*4;
    const int rB = (L&7);
    const int wB = ((L>>3)&1)*4;

    const int iters = K/32;
    for (int it = 0; it < iters; it++) {
        asm volatile("cp.async.wait_group 2;");
        __syncthreads();

        const float (*Ac)[36] = (const float(*)[36])(As + (it&3)*64);
        const float (*Bc)[36] = (const float(*)[36])(Bs + (it&3)*128);

        #pragma unroll
        for (int kb = 0; kb < 4; kb++) {
            uint32_t af[2][4];
            #pragma unroll
            for (int mi = 0; mi < 2; mi++)
                ldsm_x4(af[mi], saddr(&Ac[wm*32 + mi*16 + rA][8*kb + wA]));
            #pragma unroll
            for (int nj = 0; nj < 4; nj++) {
                uint32_t bf[2];
                ldsm_x2(bf, saddr(&Bc[wn*32 + nj*8 + rB][8*kb + wB]));
                mma_tf32(acc[0][nj], af[0], bf[0], bf[1]);
                mma_tf32(acc[1][nj], af[1], bf[0], bf[1]);
            }
        }

        if (it + 3 < iters) {
            loadA((it+3)&3, (it+3)*32);
            loadB((it+3)&3, (it+3)*32);
            CP_COMMIT();
        }
    }

    // epilogue
    #pragma unroll
    for (int mi = 0; mi < 2; mi++) {
        #pragma unroll
        for (int half = 0; half < 2; half++) {
            const int gm = m0 + wm*32 + mi*16 + gid + half*8;
            #pragma unroll
            for (int nj = 0; nj < 4; nj++) {
                const int gc = ncout0 + wn*32 + nj*8 + 2*t;   // even
                float v0 = acc[mi][nj][half*2 + 0];
                float v1 = acc[mi][nj][half*2 + 1];

                if (EPI == EPI_QKV) {
                    if (ncout0 < 512) {
                        // Q or K: rope; Q additionally folds scale*log2e
                        const int s  = gm & (SEQ - 1);
                        const int dd = gc & (DHEAD - 1);
                        const float ang = (float)s * c_invfreq[dd >> 1];
                        float sn, cs;
                        sincosf(ang, &sn, &cs);
                        const float e = v0, o = v1;
                        v0 = e*cs - o*sn;
                        v1 = o*cs + e*sn;
                        if (ncout0 < 256) { v0 *= QSCALE; v1 *= QSCALE; }
                        v0 = f2tf(v0); v1 = f2tf(v1);
                        *(float2*)&C[(size_t)gm * ldc + gc] = make_float2(v0, v1);
                    } else {
                        // V: scatter transposed bf16 into vt[b][h][d][s]
                        const int gc512 = gc - 512;
                        const int hh = gc512 >> 5, dd = gc512 & 31;
                        const size_t vb = (((size_t)(gm >> 12) * NHEAD + hh) * DHEAD + dd) * SEQ
                                          + (gm & (SEQ - 1));
                        vt[vb]       = __float2bfloat16_rn(v0);
                        vt[vb + SEQ] = __float2bfloat16_rn(v1);
                    }
                } else {
                    if (EPI == EPI_BIAS_GELU) {
                        float t0 = v0 + bias[gc], t1 = v1 + bias[gc + 1];
                        v0 = f2tf(0.5f * t0 * (1.0f + erff(t0 * 0.7071067811865476f)));
                        v1 = f2tf(0.5f * t1 * (1.0f + erff(t1 * 0.7071067811865476f)));
                    } else if (EPI == EPI_RESID) {
                        v0 += resid[(size_t)gm * ldr + gc];      // mlpin stays fp32
                        v1 += resid[(size_t)gm * ldr + gc + 1];
                    } else if (EPI == EPI_BIAS_RESID) {
                        v0 += bias[gc]     + resid[(size_t)gm * ldr + gc];
                        v1 += bias[gc + 1] + resid[(size_t)gm * ldr + gc + 1];
                    }
                    *(float2*)&C[(size_t)gm * ldc + gc] = make_float2(v0, v1);
                }
            }
        }
    }
}

// ---------------- Flash attention v5 ------------------------------------------
// QK^T tf32 mma; softmax log2-domain; P packed to bf16 IN REGISTERS (no smem);
// PV bf16 m16n8k16 with bf16 V^T tiles. 128 q-rows, 8 warps, 3-stage pipeline.
__global__ __launch_bounds__(256, 3)
void flash_attn_v5(const float* __restrict__ qkv, const __nv_bfloat16* __restrict__ vt,
                   float* __restrict__ out)
{
    extern __shared__ float sm[];
    float (*Qs)[36] = (float(*)[36])sm;                          // [128][36] f32
    float (*Ks)[36] = (float(*)[36])(sm + 128*36);               // [3*64][36] f32
    __nv_bfloat16 (*Vts)[72] =
        (__nv_bfloat16(*)[72])(sm + 128*36 + 3*64*36);           // [3*32][72] bf16

    const int tid = threadIdx.x;
    const int w = tid>>5, L = tid&31, gid = L>>2, t = L&3;
    const int b = blockIdx.y >> 3, h = blockIdx.y & 7;
    const int qbase = blockIdx.x * 128;
    const int qw = w * 16;

    const size_t qoff  = (size_t)(b*SEQ + qbase) * 768 + h*32;
    const size_t kvoff = (size_t)(b*SEQ) * 768 + h*32;
    const __nv_bfloat16* vtg = vt + (size_t)(b*NHEAD + h) * DHEAD * SEQ;

    #pragma unroll
    for (int c = 0; c < 4; c++) {
        const int ci = tid*4 + c;
        const int r = ci>>3, cc = (ci&7)*4;
        cp16(&Qs[r][cc], qkv + qoff + (size_t)r*768 + cc);
    }
    auto loadKV = [&](int stg, int kt) {
        const int kbase = kt*64;
        #pragma unroll
        for (int c = 0; c < 2; c++) {
            const int ci = tid*2 + c;
            const int r = ci>>3, cc = (ci&7)*4;       // K: 64 rows x 8 f32-chunks
            cp16(&Ks[stg*64 + r][cc], qkv + kvoff + (size_t)(kbase + r)*768 + 256 + cc);
        }
        {   // V: 32 d-rows x 8 bf16-chunks (16B = 8 halves); 256 chunks, 1/thread
            const int d = tid>>3, ch = (tid&7)*8;
            cp16(&Vts[stg*32 + d][ch], vtg + (size_t)d*SEQ + kbase + ch);
        }
    };
    loadKV(0, 0); CP_COMMIT();
    loadKV(1, 1); CP_COMMIT();
    asm volatile("cp.async.wait_group 1;");
    __syncthreads();

    uint32_t qa[4][4];
    #pragma unroll
    for (int kb = 0; kb < 4; kb++) {
        qa[kb][0] = __float_as_uint(Qs[qw + gid    ][8*kb + t]);
        qa[kb][1] = __float_as_uint(Qs[qw + gid + 8][8*kb + t]);
        qa[kb][2] = __float_as_uint(Qs[qw + gid    ][8*kb + t + 4]);
        qa[kb][3] = __float_as_uint(Qs[qw + gid + 8][8*kb + t + 4]);
    }

    // ldmatrix lane addressing
    const int rK = (L&7);
    const int wK = ((L>>3)&1)*4;
    const int L15 = L & 15;
    const int rV = L15 & 7;            // + 8*j
    const int wV = (L15>>3)*8;         // + 16*ks

    float oacc[4][4];
    #pragma unroll
    for (int j = 0; j < 4; j++)
        #pragma unroll
        for (int r = 0; r < 4; r++) oacc[j][r] = 0.f;
    float mA = -1e30f, mB = -1e30f, lA = 0.f, lB = 0.f;

    for (int kt = 0; kt < SEQ/64; kt++) {
        if (kt > 0) { asm volatile("cp.async.wait_group 1;"); }
        __syncthreads();
        if (kt + 2 < SEQ/64) { loadKV((kt+2)%3, kt+2); CP_COMMIT(); }

        const int stg = kt % 3;
        const float (*Kc)[36] = (const float(*)[36])(Ks + stg*64);
        const __nv_bfloat16 (*Vc)[72] = (const __nv_bfloat16(*)[72])(Vts + stg*32);

        // S' = (Q*scale*log2e) K^T  (tf32)
        float sa[8][4];
        #pragma unroll
        for (int j = 0; j < 8; j++)
            #pragma unroll
            for (int r = 0; r < 4; r++) sa[j][r] = 0.f;

        #pragma unroll
        for (int kb = 0; kb < 4; kb++) {
            #pragma unroll
            for (int j = 0; j < 8; j++) {
                uint32_t bf[2];
                ldsm_x2(bf, saddr(&Kc[8*j + rK][8*kb + wK]));
                mma_tf32(sa[j], qa[kb], bf[0], bf[1]);
            }
        }

        // online softmax in log2 domain (rows gid [A], gid+8 [B])
        float mxA = -1e30f, mxB = -1e30f;
        #pragma unroll
        for (int j = 0; j < 8; j++) {
            mxA = fmaxf(mxA, fmaxf(sa[j][0], sa[j][1]));
            mxB = fmaxf(mxB, fmaxf(sa[j][2], sa[j][3]));
        }
        #pragma unroll
        for (int o = 1; o <= 2; o <<= 1) {
            mxA = fmaxf(mxA, __shfl_xor_sync(0xffffffffu, mxA, o));
            mxB = fmaxf(mxB, __shfl_xor_sync(0xffffffffu, mxB, o));
        }
        const float mnA = fmaxf(mA, mxA);
        const float mnB = fmaxf(mB, mxB);
        const float corrA = ex2(mA - mnA);
        const float corrB = ex2(mB - mnB);
        mA = mnA; mB = mnB;

        // p = ex2(s' - m'), packed straight into bf16 A-fragments (no smem!)
        uint32_t pa[8][2];
        float psumA = 0.f, psumB = 0.f;
        #pragma unroll
        for (int j = 0; j < 8; j++) {
            const float p0 = ex2(sa[j][0] - mA);
            const float p1 = ex2(sa[j][1] - mA);
            const float p2 = ex2(sa[j][2] - mB);
            const float p3 = ex2(sa[j][3] - mB);
            psumA += p0 + p1;
            psumB += p2 + p3;
            pa[j][0] = pack_bf16(p0, p1);   // row gid,   k = 8j+2t, 8j+2t+1
            pa[j][1] = pack_bf16(p2, p3);   // row gid+8
        }
        lA = lA * corrA + psumA;
        lB = lB * corrB + psumB;
        #pragma unroll
        for (int j = 0; j < 4; j++) {
            oacc[j][0] *= corrA; oacc[j][1] *= corrA;
            oacc[j][2] *= corrB; oacc[j][3] *= corrB;
        }

        // O += P V : 4 k16-steps x 4 d-frags, bf16 mma, V^T ldmatrix
        #pragma unroll
        for (int ks = 0; ks < 4; ks++) {
            uint32_t af[4] = { pa[2*ks][0], pa[2*ks][1], pa[2*ks+1][0], pa[2*ks+1][1] };
            #pragma unroll
            for (int j = 0; j < 4; j++) {
                uint32_t bf[2];
                ldsm_x2(bf, saddr(&Vc[8*j + rV][16*ks + wV]));
                mma_bf16(oacc[j], af, bf[0], bf[1]);
            }
        }
    }

    #pragma unroll
    for (int o = 1; o <= 2; o <<= 1) {
        lA += __shfl_xor_sync(0xffffffffu, lA, o);
        lB += __shfl_xor_sync(0xffffffffu, lB, o);
    }
    const float invA = 1.0f / lA;
    const float invB = 1.0f / lB;

    #pragma unroll
    for (int j = 0; j < 4; j++) {
        const int gc = h*32 + 8*j + 2*t;
        const int rA2 = b*SEQ + qbase + qw + gid;
        const int rB2 = rA2 + 8;
        *(float2*)&out[(size_t)rA2 * DMODEL + gc] =
            make_float2(f2tf(oacc[j][0]*invA), f2tf(oacc[j][1]*invA));
        *(float2*)&out[(size_t)rB2 * DMODEL + gc] =
            make_float2(f2tf(oacc[j][2]*invB), f2tf(oacc[j][3]*invB));
    }
}

// ---------------- launch ------------------------------------------------------
extern "C" void kernel_launch(void* const* d_in, const int* in_sizes, int n_in,
                              void* d_out, int out_size)
{
    const float* x     = (const float*)d_in[0];
    const float* Wq    = (const float*)d_in[1];
    const float* Wk    = (const float*)d_in[2];
    const float* Wv    = (const float*)d_in[3];
    const float* Wo    = (const float*)d_in[4];
    const float* ln1_g = (const float*)d_in[5];
    const float* ln1_b = (const float*)d_in[6];
    const float* ln2_g = (const float*)d_in[7];
    const float* ln2_b = (const float*)d_in[8];
    const float* W2    = (const float*)d_in[9];
    const float* b2    = (const float*)d_in[10];
    const float* W3    = (const float*)d_in[11];
    const float* b3    = (const float*)d_in[12];
    float* out = (float*)d_out;

    float *xn, *qkv, *attn, *mlpin, *yn, *hbuf, *wr;
    __nv_bfloat16* vt;
    cudaGetSymbolAddress((void**)&xn,    g_xn);
    cudaGetSymbolAddress((void**)&qkv,   g_qkv);
    cudaGetSymbolAddress((void**)&vt,    g_vt);
    cudaGetSymbolAddress((void**)&attn,  g_attn);
    cudaGetSymbolAddress((void**)&mlpin, g_mlpin);
    cudaGetSymbolAddress((void**)&yn,    g_yn);
    cudaGetSymbolAddress((void**)&hbuf,  g_h);
    cudaGetSymbolAddress((void**)&wr,    g_wr);

    const float* wr_q = wr;
    const float* wr_k = wr + WSMALL;
    const float* wr_v = wr + 2*WSMALL;
    const float* wr_o = wr + 3*WSMALL;
    const float* wr_2 = wr + 4*WSMALL;
    const float* wr_3 = wr + 4*WSMALL + WBIG;

    const int smGemm = 4*(64 + 128)*36*4;                          // 110592
    const int smAttn = 128*36*4 + 3*64*36*4 + 3*32*72*2;           // 59904

    cudaFuncSetAttribute(gemm_v3<EPI_QKV>,        cudaFuncAttributeMaxDynamicSharedMemorySize, smGemm);
    cudaFuncSetAttribute(gemm_v3<EPI_BIAS_GELU>,  cudaFuncAttributeMaxDynamicSharedMemorySize, smGemm);
    cudaFuncSetAttribute(gemm_v3<EPI_RESID>,      cudaFuncAttributeMaxDynamicSharedMemorySize, smGemm);
    cudaFuncSetAttribute(gemm_v3<EPI_BIAS_RESID>, cudaFuncAttributeMaxDynamicSharedMemorySize, smGemm);
    cudaFuncSetAttribute(flash_attn_v5,           cudaFuncAttributeMaxDynamicSharedMemorySize, smAttn);

    // weight rounding (deterministic, ~3MB traffic)
    round_weights<<<(4*WSMALL + 2*WBIG)/4/256, 256>>>(Wq, Wk, Wv, Wo, W2, W3, wr);

    // LN1 (tf32-rounded output)
    ln_kernel<<<NROW, 256>>>(x, ln1_g, ln1_b, xn);

    // Fused QKV projections: Q (rope + scale*log2e), K (rope), V -> bf16 vt
    gemm_v3<EPI_QKV><<<dim3(6, NROW/64), 256, smGemm>>>(
        xn, DMODEL, wr_q, DMODEL, qkv, 768, DMODEL, wr_k, wr_v, 0, vt);

    // attention
    flash_attn_v5<<<dim3(SEQ/128, BATCH*NHEAD), 256, smAttn>>>(qkv, vt, attn);

    // output projection + residual -> mlp_in (fp32)
    gemm_v3<EPI_RESID><<<dim3(2, NROW/64), 256, smGemm>>>(
        attn, DMODEL, wr_o, DMODEL, mlpin, DMODEL, DMODEL, nullptr, x, DMODEL, nullptr);

    // LN2 (rounded output)
    ln_kernel<<<NROW, 256>>>(mlpin, ln2_g, ln2_b, yn);

    // MLP
    gemm_v3<EPI_BIAS_GELU><<<dim3(8, NROW/64), 256, smGemm>>>(
        yn, DMODEL, wr_2, DMODEL, hbuf, DMLP, DMODEL, b2, nullptr, 0, nullptr);
    gemm_v3<EPI_BIAS_RESID><<<dim3(2, NROW/64), 256, smGemm>>>(
        hbuf, DMLP, wr_3, DMLP, out, DMODEL, DMLP, b3, mlpin, DMODEL, nullptr);
}

// round 11
// speedup vs baseline: 2.0135x; 1.4969x over previous
#include <cuda_runtime.h>
#include <cuda_fp16.h>
#include <math.h>
#include <stdint.h>

#define BATCH 2
#define SEQ   4096
#define DMODEL 256
#define NHEAD 8
#define DHEAD 32
#define DMLP  1024
#define NROW  (BATCH*SEQ)   // 8192

// ---------------- scratch (static device globals; no allocation) -------------
__device__ __half g_xn[NROW*DMODEL];
__device__ __half g_qh[NROW*DMODEL];                 // Q (rope+scale*log2e), half
__device__ __half g_kh[NROW*DMODEL];                 // K (rope), half
__device__ __half g_vt[BATCH*NHEAD*DHEAD*SEQ];       // V^T: [b][h][d][s], half
__device__ __half g_attn[NROW*DMODEL];
__device__ float  g_mlpin[NROW*DMODEL];
__device__ __half g_yn[NROW*DMODEL];
__device__ __half g_hb[NROW*DMLP];
#define WSMALL (DMODEL*DMODEL)        // 65536
#define WBIG   (DMLP*DMODEL)          // 262144
__device__ __half g_wr[4*WSMALL + 2*WBIG];           // half weights

// inv_freq[i] = 10000^(-i/16) = 10^(-i/4)
__constant__ float c_invfreq[16] = {
    1.0f, 0.5623413251903491f, 0.31622776601683794f, 0.17782794100389228f,
    0.1f, 0.05623413251903491f, 0.031622776601683794f, 0.017782794100389228f,
    0.01f, 0.005623413251903491f, 0.0031622776601683794f, 0.0017782794100389228f,
    0.001f, 0.0005623413251903491f, 0.00031622776601683794f, 0.00017782794100389227f
};

// (1/sqrt(32)) * log2(e): folded into Q so softmax runs in log2 domain
#define QSCALE 0.2550348754541408f

__device__ __forceinline__ float ex2(float x) {
    float y;
    asm("ex2.approx.f32 %0, %1;" : "=f"(y) : "f"(x));
    return y;
}
// pack two fp32 -> f16x2 (lo = first k, hi = second k)
__device__ __forceinline__ uint32_t pack_f16(float lo, float hi) {
    uint32_t r;
    asm("cvt.rn.f16x2.f32 %0, %1, %2;" : "=r"(r) : "f"(hi), "f"(lo));
    return r;
}
__device__ __forceinline__ void cp16(void* smem_dst, const void* gmem_src) {
    uint32_t s = (uint32_t)__cvta_generic_to_shared(smem_dst);
    asm volatile("cp.async.cg.shared.global [%0], [%1], 16;" :: "r"(s), "l"(gmem_src));
}
#define CP_COMMIT() asm volatile("cp.async.commit_group;")
__device__ __forceinline__ uint32_t saddr(const void* p) {
    return (uint32_t)__cvta_generic_to_shared(p);
}
__device__ __forceinline__ void ldsm_x4(uint32_t* r, uint32_t a) {
    asm volatile("ldmatrix.sync.aligned.m8n8.x4.shared.b16 {%0,%1,%2,%3}, [%4];"
        : "=r"(r[0]), "=r"(r[1]), "=r"(r[2]), "=r"(r[3]) : "r"(a));
}
__device__ __forceinline__ void ldsm_x2(uint32_t* r, uint32_t a) {
    asm volatile("ldmatrix.sync.aligned.m8n8.x2.shared.b16 {%0,%1}, [%2];"
        : "=r"(r[0]), "=r"(r[1]) : "r"(a));
}
// D += A*B, m16n8k16 fp16 inputs, fp32 accumulate
__device__ __forceinline__ void mma_f16(float* d, const uint32_t* a, uint32_t b0, uint32_t b1) {
    asm volatile("mma.sync.aligned.m16n8k16.row.col.f32.f16.f16.f32 "
        "{%0,%1,%2,%3}, {%4,%5,%6,%7}, {%8,%9}, {%0,%1,%2,%3};\n"
        : "+f"(d[0]), "+f"(d[1]), "+f"(d[2]), "+f"(d[3])
        : "r"(a[0]), "r"(a[1]), "r"(a[2]), "r"(a[3]), "r"(b0), "r"(b1));
}

// ---------------- weight conversion fp32 -> fp16 ------------------------------
__global__ void round_weights(const float* __restrict__ Wq, const float* __restrict__ Wk,
                              const float* __restrict__ Wv, const float* __restrict__ Wo,
                              const float* __restrict__ W2, const float* __restrict__ W3,
                              __half* __restrict__ out)
{
    const int i = blockIdx.x * blockDim.x + threadIdx.x;   // float4 index
    const int n1 = WSMALL / 4;
    const float4* src;
    int local;
    if (i < 4*n1) {
        const float* w4[4] = {Wq, Wk, Wv, Wo};
        src = (const float4*)w4[i / n1];
        local = i % n1;
    } else if (i < 4*n1 + WBIG/4) {
        src = (const float4*)W2; local = i - 4*n1;
    } else {
        src = (const float4*)W3; local = i - 4*n1 - WBIG/4;
    }
    float4 v = src[local];
    __half2 h0 = __floats2half2_rn(v.x, v.y);
    __half2 h1 = __floats2half2_rn(v.z, v.w);
    ((uint2*)out)[i] = make_uint2(*(uint32_t*)&h0, *(uint32_t*)&h1);
}

// ---------------- LayerNorm: one block per row, half output -------------------
__global__ void ln_kernel(const float* __restrict__ x, const float* __restrict__ g,
                          const float* __restrict__ b, __half* __restrict__ out)
{
    const int row = blockIdx.x;
    const int t   = threadIdx.x;
    const float v = x[row*DMODEL + t];
    __shared__ float red1[8];
    __shared__ float red2[8];

    float s = v;
    #pragma unroll
    for (int o = 16; o > 0; o >>= 1) s += __shfl_xor_sync(0xffffffffu, s, o);
    if ((t & 31) == 0) red1[t >> 5] = s;
    __syncthreads();
    float mean = 0.f;
    #pragma unroll
    for (int i = 0; i < 8; i++) mean += red1[i];
    mean *= (1.0f/DMODEL);
    const float d = v - mean;

    float s2 = d*d;
    #pragma unroll
    for (int o = 16; o > 0; o >>= 1) s2 += __shfl_xor_sync(0xffffffffu, s2, o);
    if ((t & 31) == 0) red2[t >> 5] = s2;
    __syncthreads();
    float var = 0.f;
    #pragma unroll
    for (int i = 0; i < 8; i++) var += red2[i];
    var *= (1.0f/DMODEL);

    out[row*DMODEL + t] = __float2half_rn(d * rsqrtf(var + 1e-5f) * g[t] + b[t]);
}

// ---------------- GEMM (C = A * B^T), fp16 mma, 4-stage cp.async, ldmatrix ----
// A: half [M,K] row-major; B: half [N,K] row-major.
// Tile 64x128x32, 256 thr, 8 warps 2(m)x4(n), warp 32x32, k16 mma.
enum { EPI_QKV=0, EPI_BIAS_GELU=1, EPI_RESID=2, EPI_BIAS_RESID=3 };

template<int EPI>
__global__ __launch_bounds__(256, 3)
void gemm_h(const __half* __restrict__ A, int lda,
            const __half* __restrict__ Bw, int ldb,
            int K,
            float* __restrict__ Cf, __half* __restrict__ Ch, int ldc,
            const float* __restrict__ bias,
            const float* __restrict__ resid, int ldr,
            __half* __restrict__ qh, __half* __restrict__ kh, __half* __restrict__ vt)
{
    extern __shared__ __half smh[];
    __half (*As)[40] = (__half(*)[40])smh;                 // [4*64][40]
    __half (*Bs)[40] = (__half(*)[40])(smh + 4*64*40);     // [4*128][40]

    const int tid = threadIdx.x;
    const int w = tid>>5, L = tid&31, gid = L>>2, t = L&3;
    const int wm = w>>2, wn = w&3;
    const int m0 = blockIdx.y * 64;
    const int bx = blockIdx.x;

    const __half* Bmat;
    int nlocal0, ncout0;
    if (EPI == EPI_QKV) {
        Bmat = Bw + (size_t)(bx >> 1) * WSMALL;   // wq, wk, wv contiguous
        nlocal0 = (bx & 1) * 128;
        ncout0  = bx * 128;
    } else {
        Bmat = Bw;
        nlocal0 = bx * 128;
        ncout0  = nlocal0;
    }

    float acc[2][4][4];
    #pragma unroll
    for (int i = 0; i < 2; i++)
        #pragma unroll
        for (int j = 0; j < 4; j++)
            #pragma unroll
            for (int r = 0; r < 4; r++) acc[i][j][r] = 0.f;

    // A tile: 64 rows x 32 halves = 256 16B-chunks (1/thread)
    auto loadA = [&](int stg, int k0) {
        const int r = tid>>2, cc = (tid&3)*8;
        cp16(&As[stg*64 + r][cc], A + (size_t)(m0+r)*lda + k0 + cc);
    };
    // B tile: 128 rows x 32 halves = 512 chunks (2/thread)
    auto loadB = [&](int stg, int k0) {
        #pragma unroll
        for (int c = 0; c < 2; c++) {
            const int ci = tid*2 + c;
            const int r = ci>>2, cc = (ci&3)*8;
            cp16(&Bs[stg*128 + r][cc], Bmat + (size_t)(nlocal0+r)*ldb + k0 + cc);
        }
    };

    loadA(0, 0);  loadB(0, 0);  CP_COMMIT();
    loadA(1, 32); loadB(1, 32); CP_COMMIT();
    loadA(2, 64); loadB(2, 64); CP_COMMIT();

    // ldmatrix lane addressing (fp16 k16 fragments)
    const int rA = L & 15;
    const int wA = ((L>>4)&1)*8;
    const int rB = L & 7;
    const int wB = ((L>>3)&1)*8;

    const int iters = K/32;
    for (int it = 0; it < iters; it++) {
        asm volatile("cp.async.wait_group 2;");
        __syncthreads();

        const __half (*Ac)[40] = (const __half(*)[40])(As + (it&3)*64);
        const __half (*Bc)[40] = (const __half(*)[40])(Bs + (it&3)*128);

        #pragma unroll
        for (int kb = 0; kb < 2; kb++) {
            uint32_t af[2][4];
            #pragma unroll
            for (int mi = 0; mi < 2; mi++)
                ldsm_x4(af[mi], saddr(&Ac[wm*32 + mi*16 + rA][16*kb + wA]));
            #pragma unroll
            for (int nj = 0; nj < 4; nj++) {
                uint32_t bf[2];
                ldsm_x2(bf, saddr(&Bc[wn*32 + nj*8 + rB][16*kb + wB]));
                mma_f16(acc[0][nj], af[0], bf[0], bf[1]);
                mma_f16(acc[1][nj], af[1], bf[0], bf[1]);
            }
        }

        if (it + 3 < iters) {
            loadA((it+3)&3, (it+3)*32);
            loadB((it+3)&3, (it+3)*32);
            CP_COMMIT();
        }
    }

    // epilogue
    #pragma unroll
    for (int mi = 0; mi < 2; mi++) {
        #pragma unroll
        for (int half_ = 0; half_ < 2; half_++) {
            const int gm = m0 + wm*32 + mi*16 + gid + half_*8;
            #pragma unroll
            for (int nj = 0; nj < 4; nj++) {
                const int gc = ncout0 + wn*32 + nj*8 + 2*t;   // even
                float v0 = acc[mi][nj][half_*2 + 0];
                float v1 = acc[mi][nj][half_*2 + 1];

                if (EPI == EPI_QKV) {
                    if (ncout0 < 512) {
                        // Q or K: rope; Q additionally folds scale*log2e
                        const int s  = gm & (SEQ - 1);
                        const int dd = gc & (DHEAD - 1);
                        const float ang = (float)s * c_invfreq[dd >> 1];
                        float sn, cs;
                        sincosf(ang, &sn, &cs);
                        const float e = v0, o = v1;
                        v0 = e*cs - o*sn;
                        v1 = o*cs + e*sn;
                        __half2 hv;
                        if (ncout0 < 256) {
                            hv = __floats2half2_rn(v0*QSCALE, v1*QSCALE);
                            *(__half2*)&qh[(size_t)gm*DMODEL + gc] = hv;
                        } else {
                            hv = __floats2half2_rn(v0, v1);
                            *(__half2*)&kh[(size_t)gm*DMODEL + (gc - 256)] = hv;
                        }
                    } else {
                        // V: scatter transposed half into vt[b][h][d][s]
                        const int gc512 = gc - 512;
                        const int hh = gc512 >> 5, dd = gc512 & 31;
                        const size_t vb = (((size_t)(gm >> 12) * NHEAD + hh) * DHEAD + dd) * SEQ
                                          + (gm & (SEQ - 1));
                        vt[vb]       = __float2half_rn(v0);
                        vt[vb + SEQ] = __float2half_rn(v1);
                    }
                } else if (EPI == EPI_BIAS_GELU) {
                    float t0 = v0 + bias[gc], t1 = v1 + bias[gc + 1];
                    t0 = 0.5f * t0 * (1.0f + erff(t0 * 0.7071067811865476f));
                    t1 = 0.5f * t1 * (1.0f + erff(t1 * 0.7071067811865476f));
                    *(__half2*)&Ch[(size_t)gm*ldc + gc] = __floats2half2_rn(t0, t1);
                } else if (EPI == EPI_RESID) {
                    v0 += resid[(size_t)gm * ldr + gc];
                    v1 += resid[(size_t)gm * ldr + gc + 1];
                    *(float2*)&Cf[(size_t)gm*ldc + gc] = make_float2(v0, v1);
                } else {  // EPI_BIAS_RESID
                    v0 += bias[gc]     + resid[(size_t)gm * ldr + gc];
                    v1 += bias[gc + 1] + resid[(size_t)gm * ldr + gc + 1];
                    *(float2*)&Cf[(size_t)gm*ldc + gc] = make_float2(v0, v1);
                }
            }
        }
    }
}

// ---------------- Flash attention v6: all-fp16 operands, fp32 accum ----------
// QK^T fp16 m16n8k16; softmax log2-domain; P packed f16 in registers;
// PV fp16 m16n8k16. 128 q-rows, 8 warps, 3-stage pipeline.
__global__ __launch_bounds__(256, 3)
void flash_attn_v6(const __half* __restrict__ qh, const __half* __restrict__ kh,
                   const __half* __restrict__ vt, __half* __restrict__ out)
{
    extern __shared__ __half smh[];
    __half (*Qs)[40]  = (__half(*)[40])smh;                       // [128][40]
    __half (*Ks)[40]  = (__half(*)[40])(smh + 128*40);            // [3*64][40]
    __half (*Vts)[72] = (__half(*)[72])(smh + 128*40 + 3*64*40);  // [3*32][72]

    const int tid = threadIdx.x;
    const int w = tid>>5, L = tid&31, gid = L>>2, t = L&3;
    const int b = blockIdx.y >> 3, h = blockIdx.y & 7;
    const int qbase = blockIdx.x * 128;
    const int qw = w * 16;

    const __half* qg  = qh + (size_t)(b*SEQ + qbase)*DMODEL + h*32;
    const __half* kg  = kh + (size_t)(b*SEQ)*DMODEL + h*32;
    const __half* vtg = vt + (size_t)(b*NHEAD + h) * DHEAD * SEQ;

    // Q tile: 128 rows x 32 halves = 512 chunks (2/thread)
    #pragma unroll
    for (int c = 0; c < 2; c++) {
        const int ci = tid*2 + c;
        const int r = ci>>2, cc = (ci&3)*8;
        cp16(&Qs[r][cc], qg + (size_t)r*DMODEL + cc);
    }
    auto loadKV = [&](int stg, int kt) {
        const int kbase = kt*64;
        {   // K: 64 rows x 32 halves = 256 chunks (1/thread)
            const int r = tid>>2, cc = (tid&3)*8;
            cp16(&Ks[stg*64 + r][cc], kg + (size_t)(kbase + r)*DMODEL + cc);
        }
        {   // V^T: 32 d-rows x 64 halves = 256 chunks (1/thread)
            const int d = tid>>3, ch = (tid&7)*8;
            cp16(&Vts[stg*32 + d][ch], vtg + (size_t)d*SEQ + kbase + ch);
        }
    };
    loadKV(0, 0); CP_COMMIT();
    loadKV(1, 1); CP_COMMIT();
    asm volatile("cp.async.wait_group 1;");
    __syncthreads();

    // hoist Q fragments: qa[kb][4], kb in {0,1} (k16 each)
    uint32_t qa[2][4];
    #pragma unroll
    for (int kb = 0; kb < 2; kb++)
        ldsm_x4(qa[kb], saddr(&Qs[qw + (L&15)][16*kb + ((L>>4)&1)*8]));

    // ldmatrix lane addressing
    const int rK = L & 7;
    const int wK = ((L>>3)&1)*8;
    const int L15 = L & 15;
    const int rV = L15 & 7;
    const int wV = (L15>>3)*8;

    float oacc[4][4];
    #pragma unroll
    for (int j = 0; j < 4; j++)
        #pragma unroll
        for (int r = 0; r < 4; r++) oacc[j][r] = 0.f;
    float mA = -1e30f, mB = -1e30f, lA = 0.f, lB = 0.f;

    for (int kt = 0; kt < SEQ/64; kt++) {
        if (kt > 0) { asm volatile("cp.async.wait_group 1;"); }
        __syncthreads();
        if (kt + 2 < SEQ/64) { loadKV((kt+2)%3, kt+2); CP_COMMIT(); }

        const int stg = kt % 3;
        const __half (*Kc)[40]  = (const __half(*)[40])(Ks + stg*64);
        const __half (*Vc)[72]  = (const __half(*)[72])(Vts + stg*32);

        // S' = (Q*scale*log2e) K^T  (fp16 mma, fp32 acc)
        float sa[8][4];
        #pragma unroll
        for (int j = 0; j < 8; j++)
            #pragma unroll
            for (int r = 0; r < 4; r++) sa[j][r] = 0.f;

        #pragma unroll
        for (int kb = 0; kb < 2; kb++) {
            #pragma unroll
            for (int j = 0; j < 8; j++) {
                uint32_t bf[2];
                ldsm_x2(bf, saddr(&Kc[8*j + rK][16*kb + wK]));
                mma_f16(sa[j], qa[kb], bf[0], bf[1]);
            }
        }

        // online softmax in log2 domain (rows gid [A], gid+8 [B])
        float mxA = -1e30f, mxB = -1e30f;
        #pragma unroll
        for (int j = 0; j < 8; j++) {
            mxA = fmaxf(mxA, fmaxf(sa[j][0], sa[j][1]));
            mxB = fmaxf(mxB, fmaxf(sa[j][2], sa[j][3]));
        }
        #pragma unroll
        for (int o = 1; o <= 2; o <<= 1) {
            mxA = fmaxf(mxA, __shfl_xor_sync(0xffffffffu, mxA, o));
            mxB = fmaxf(mxB, __shfl_xor_sync(0xffffffffu, mxB, o));
        }
        const float mnA = fmaxf(mA, mxA);
        const float mnB = fmaxf(mB, mxB);
        const float corrA = ex2(mA - mnA);
        const float corrB = ex2(mB - mnB);
        mA = mnA; mB = mnB;

        // p = ex2(s' - m'), packed straight into f16 A-fragments (no smem)
        uint32_t pa[8][2];
        float psumA = 0.f, psumB = 0.f;
        #pragma unroll
        for (int j = 0; j < 8; j++) {
            const float p0 = ex2(sa[j][0] - mA);
            const float p1 = ex2(sa[j][1] - mA);
            const float p2 = ex2(sa[j][2] - mB);
            const float p3 = ex2(sa[j][3] - mB);
            psumA += p0 + p1;
            psumB += p2 + p3;
            pa[j][0] = pack_f16(p0, p1);   // row gid,   k = 8j+2t, +1
            pa[j][1] = pack_f16(p2, p3);   // row gid+8
        }
        lA = lA * corrA + psumA;
        lB = lB * corrB + psumB;
        #pragma unroll
        for (int j = 0; j < 4; j++) {
            oacc[j][0] *= corrA; oacc[j][1] *= corrA;
            oacc[j][2] *= corrB; oacc[j][3] *= corrB;
        }

        // O += P V : 4 k16-steps x 4 d-frags, fp16 mma, V^T ldmatrix
        #pragma unroll
        for (int ks = 0; ks < 4; ks++) {
            uint32_t af[4] = { pa[2*ks][0], pa[2*ks][1], pa[2*ks+1][0], pa[2*ks+1][1] };
            #pragma unroll
            for (int j = 0; j < 4; j++) {
                uint32_t bf[2];
                ldsm_x2(bf, saddr(&Vc[8*j + rV][16*ks + wV]));
                mma_f16(oacc[j], af, bf[0], bf[1]);
            }
        }
    }

    #pragma unroll
    for (int o = 1; o <= 2; o <<= 1) {
        lA += __shfl_xor_sync(0xffffffffu, lA, o);
        lB += __shfl_xor_sync(0xffffffffu, lB, o);
    }
    const float invA = 1.0f / lA;
    const float invB = 1.0f / lB;

    #pragma unroll
    for (int j = 0; j < 4; j++) {
        const int gc = h*32 + 8*j + 2*t;
        const int rA2 = b*SEQ + qbase + qw + gid;
        const int rB2 = rA2 + 8;
        *(__half2*)&out[(size_t)rA2 * DMODEL + gc] =
            __floats2half2_rn(oacc[j][0]*invA, oacc[j][1]*invA);
        *(__half2*)&out[(size_t)rB2 * DMODEL + gc] =
            __floats2half2_rn(oacc[j][2]*invB, oacc[j][3]*invB);
    }
}

// ---------------- launch ------------------------------------------------------
extern "C" void kernel_launch(void* const* d_in, const int* in_sizes, int n_in,
                              void* d_out, int out_size)
{
    const float* x     = (const float*)d_in[0];
    const float* Wq    = (const float*)d_in[1];
    const float* Wk    = (const float*)d_in[2];
    const float* Wv    = (const float*)d_in[3];
    const float* Wo    = (const float*)d_in[4];
    const float* ln1_g = (const float*)d_in[5];
    const float* ln1_b = (const float*)d_in[6];
    const float* ln2_g = (const float*)d_in[7];
    const float* ln2_b = (const float*)d_in[8];
    const float* W2    = (const float*)d_in[9];
    const float* b2    = (const float*)d_in[10];
    const float* W3    = (const float*)d_in[11];
    const float* b3    = (const float*)d_in[12];
    float* out = (float*)d_out;

    __half *xn, *qh, *kh, *vt, *attn, *yn, *hbuf, *wr;
    float *mlpin;
    cudaGetSymbolAddress((void**)&xn,    g_xn);
    cudaGetSymbolAddress((void**)&qh,    g_qh);
    cudaGetSymbolAddress((void**)&kh,    g_kh);
    cudaGetSymbolAddress((void**)&vt,    g_vt);
    cudaGetSymbolAddress((void**)&attn,  g_attn);
    cudaGetSymbolAddress((void**)&mlpin, g_mlpin);
    cudaGetSymbolAddress((void**)&yn,    g_yn);
    cudaGetSymbolAddress((void**)&hbuf,  g_hb);
    cudaGetSymbolAddress((void**)&wr,    g_wr);

    const __half* wr_q = wr;                       // wq, wk, wv contiguous
    const __half* wr_o = wr + 3*WSMALL;
    const __half* wr_2 = wr + 4*WSMALL;
    const __half* wr_3 = wr + 4*WSMALL + WBIG;

    const int smGemm = (4*64*40 + 4*128*40) * 2;                   // 61440
    const int smAttn = (128*40 + 3*64*40 + 3*32*72) * 2;           // 39424

    cudaFuncSetAttribute(gemm_h<EPI_QKV>,        cudaFuncAttributeMaxDynamicSharedMemorySize, smGemm);
    cudaFuncSetAttribute(gemm_h<EPI_BIAS_GELU>,  cudaFuncAttributeMaxDynamicSharedMemorySize, smGemm);
    cudaFuncSetAttribute(gemm_h<EPI_RESID>,      cudaFuncAttributeMaxDynamicSharedMemorySize, smGemm);
    cudaFuncSetAttribute(gemm_h<EPI_BIAS_RESID>, cudaFuncAttributeMaxDynamicSharedMemorySize, smGemm);
    cudaFuncSetAttribute(flash_attn_v6,          cudaFuncAttributeMaxDynamicSharedMemorySize, smAttn);

    // weight conversion (deterministic)
    round_weights<<<(4*WSMALL + 2*WBIG)/4/256, 256>>>(Wq, Wk, Wv, Wo, W2, W3, wr);

    // LN1 -> half
    ln_kernel<<<NROW, 256>>>(x, ln1_g, ln1_b, xn);

    // Fused QKV projections: Q (rope+scale), K (rope), V -> half V^T
    gemm_h<EPI_QKV><<<dim3(6, NROW/64), 256, smGemm>>>(
        xn, DMODEL, wr_q, DMODEL, DMODEL,
        nullptr, nullptr, 0, nullptr, nullptr, 0, qh, kh, vt);

    // attention -> half
    flash_attn_v6<<<dim3(SEQ/128, BATCH*NHEAD), 256, smAttn>>>(qh, kh, vt, attn);

    // output projection + residual -> mlp_in (fp32)
    gemm_h<EPI_RESID><<<dim3(2, NROW/64), 256, smGemm>>>(
        attn, DMODEL, wr_o, DMODEL, DMODEL,
        mlpin, nullptr, DMODEL, nullptr, x, DMODEL, nullptr, nullptr, nullptr);

    // LN2 -> half
    ln_kernel<<<NROW, 256>>>(mlpin, ln2_g, ln2_b, yn);

    // MLP
    gemm_h<EPI_BIAS_GELU><<<dim3(8, NROW/64), 256, smGemm>>>(
        yn, DMODEL, wr_2, DMODEL, DMODEL,
        nullptr, hbuf, DMLP, b2, nullptr, 0, nullptr, nullptr, nullptr);
    gemm_h<EPI_BIAS_RESID><<<dim3(2, NROW/64), 256, smGemm>>>(
        hbuf, DMLP, wr_3, DMLP, DMLP,
        out, nullptr, DMODEL, b3, mlpin, DMODEL, nullptr, nullptr, nullptr);
}

// round 12
// speedup vs baseline: 2.1677x; 1.0766x over previous
#include <cuda_runtime.h>
#include <cuda_fp16.h>
#include <math.h>
#include <stdint.h>

#define BATCH 2
#define SEQ   4096
#define DMODEL 256
#define NHEAD 8
#define DHEAD 32
#define DMLP  1024
#define NROW  (BATCH*SEQ)   // 8192

// ---------------- scratch (static device globals; no allocation) -------------
__device__ __half g_xn[NROW*DMODEL];
__device__ __half g_qh[NROW*DMODEL];                 // Q (rope+scale*log2e), half
__device__ __half g_kh[NROW*DMODEL];                 // K (rope), half
__device__ __half g_vt[BATCH*NHEAD*DHEAD*SEQ];       // V^T: [b][h][d][s], half
__device__ __half g_attn[NROW*DMODEL];
__device__ float  g_mlpin[NROW*DMODEL];
__device__ __half g_yn[NROW*DMODEL];
__device__ __half g_hb[NROW*DMLP];
#define WSMALL (DMODEL*DMODEL)        // 65536
#define WBIG   (DMLP*DMODEL)          // 262144
__device__ __half g_wr[4*WSMALL + 2*WBIG];           // half weights

// inv_freq[i] = 10000^(-i/16) = 10^(-i/4)
__constant__ float c_invfreq[16] = {
    1.0f, 0.5623413251903491f, 0.31622776601683794f, 0.17782794100389228f,
    0.1f, 0.05623413251903491f, 0.031622776601683794f, 0.017782794100389228f,
    0.01f, 0.005623413251903491f, 0.0031622776601683794f, 0.0017782794100389228f,
    0.001f, 0.0005623413251903491f, 0.00031622776601683794f, 0.00017782794100389227f
};

// (1/sqrt(32)) * log2(e): folded into Q so softmax runs in log2 domain
#define QSCALE 0.2550348754541408f

__device__ __forceinline__ float ex2(float x) {
    float y;
    asm("ex2.approx.f32 %0, %1;" : "=f"(y) : "f"(x));
    return y;
}
// pack two fp32 -> f16x2 (lo = first k, hi = second k)
__device__ __forceinline__ uint32_t pack_f16(float lo, float hi) {
    uint32_t r;
    asm("cvt.rn.f16x2.f32 %0, %1, %2;" : "=r"(r) : "f"(hi), "f"(lo));
    return r;
}
// two ex2 in one MUFU op
__device__ __forceinline__ uint32_t hex2(uint32_t x) {
    uint32_t r;
    asm("ex2.approx.f16x2 %0, %1;" : "=r"(r) : "r"(x));
    return r;
}
__device__ __forceinline__ void cp16(void* smem_dst, const void* gmem_src) {
    uint32_t s = (uint32_t)__cvta_generic_to_shared(smem_dst);
    asm volatile("cp.async.cg.shared.global [%0], [%1], 16;" :: "r"(s), "l"(gmem_src));
}
#define CP_COMMIT() asm volatile("cp.async.commit_group;")
__device__ __forceinline__ uint32_t saddr(const void* p) {
    return (uint32_t)__cvta_generic_to_shared(p);
}
__device__ __forceinline__ void ldsm_x4(uint32_t* r, uint32_t a) {
    asm volatile("ldmatrix.sync.aligned.m8n8.x4.shared.b16 {%0,%1,%2,%3}, [%4];"
        : "=r"(r[0]), "=r"(r[1]), "=r"(r[2]), "=r"(r[3]) : "r"(a));
}
__device__ __forceinline__ void ldsm_x2(uint32_t* r, uint32_t a) {
    asm volatile("ldmatrix.sync.aligned.m8n8.x2.shared.b16 {%0,%1}, [%2];"
        : "=r"(r[0]), "=r"(r[1]) : "r"(a));
}
// D += A*B, m16n8k16 fp16 inputs, fp32 accumulate
__device__ __forceinline__ void mma_f16(float* d, const uint32_t* a, uint32_t b0, uint32_t b1) {
    asm volatile("mma.sync.aligned.m16n8k16.row.col.f32.f16.f16.f32 "
        "{%0,%1,%2,%3}, {%4,%5,%6,%7}, {%8,%9}, {%0,%1,%2,%3};\n"
        : "+f"(d[0]), "+f"(d[1]), "+f"(d[2]), "+f"(d[3])
        : "r"(a[0]), "r"(a[1]), "r"(a[2]), "r"(a[3]), "r"(b0), "r"(b1));
}

// ---------------- weight conversion fp32 -> fp16 ------------------------------
__global__ void round_weights(const float* __restrict__ Wq, const float* __restrict__ Wk,
                              const float* __restrict__ Wv, const float* __restrict__ Wo,
                              const float* __restrict__ W2, const float* __restrict__ W3,
                              __half* __restrict__ out)
{
    const int i = blockIdx.x * blockDim.x + threadIdx.x;   // float4 index
    const int n1 = WSMALL / 4;
    const float4* src;
    int local;
    if (i < 4*n1) {
        const float* w4[4] = {Wq, Wk, Wv, Wo};
        src = (const float4*)w4[i / n1];
        local = i % n1;
    } else if (i < 4*n1 + WBIG/4) {
        src = (const float4*)W2; local = i - 4*n1;
    } else {
        src = (const float4*)W3; local = i - 4*n1 - WBIG/4;
    }
    float4 v = src[local];
    __half2 h0 = __floats2half2_rn(v.x, v.y);
    __half2 h1 = __floats2half2_rn(v.z, v.w);
    ((uint2*)out)[i] = make_uint2(*(uint32_t*)&h0, *(uint32_t*)&h1);
}

// ---------------- LayerNorm: one block per row, half output -------------------
__global__ void ln_kernel(const float* __restrict__ x, const float* __restrict__ g,
                          const float* __restrict__ b, __half* __restrict__ out)
{
    const int row = blockIdx.x;
    const int t   = threadIdx.x;
    const float v = x[row*DMODEL + t];
    __shared__ float red1[8];
    __shared__ float red2[8];

    float s = v;
    #pragma unroll
    for (int o = 16; o > 0; o >>= 1) s += __shfl_xor_sync(0xffffffffu, s, o);
    if ((t & 31) == 0) red1[t >> 5] = s;
    __syncthreads();
    float mean = 0.f;
    #pragma unroll
    for (int i = 0; i < 8; i++) mean += red1[i];
    mean *= (1.0f/DMODEL);
    const float d = v - mean;

    float s2 = d*d;
    #pragma unroll
    for (int o = 16; o > 0; o >>= 1) s2 += __shfl_xor_sync(0xffffffffu, s2, o);
    if ((t & 31) == 0) red2[t >> 5] = s2;
    __syncthreads();
    float var = 0.f;
    #pragma unroll
    for (int i = 0; i < 8; i++) var += red2[i];
    var *= (1.0f/DMODEL);

    out[row*DMODEL + t] = __float2half_rn(d * rsqrtf(var + 1e-5f) * g[t] + b[t]);
}

// ---------------- GEMM (C = A * B^T), fp16 mma, 4-stage cp.async, ldmatrix ----
// A: half [M,K] row-major; B: half [N,K] row-major.
// Tile 64x128x32, 256 thr, 8 warps 2(m)x4(n), warp 32x32, k16 mma.
enum { EPI_QKV=0, EPI_BIAS_GELU=1, EPI_RESID=2, EPI_BIAS_RESID=3 };

template<int EPI>
__global__ __launch_bounds__(256, 3)
void gemm_h(const __half* __restrict__ A, int lda,
            const __half* __restrict__ Bw, int ldb,
            int K,
            float* __restrict__ Cf, __half* __restrict__ Ch, int ldc,
            const float* __restrict__ bias,
            const float* __restrict__ resid, int ldr,
            __half* __restrict__ qh, __half* __restrict__ kh, __half* __restrict__ vt)
{
    extern __shared__ __half smh[];
    __half (*As)[40] = (__half(*)[40])smh;                 // [4*64][40]
    __half (*Bs)[40] = (__half(*)[40])(smh + 4*64*40);     // [4*128][40]

    const int tid = threadIdx.x;
    const int w = tid>>5, L = tid&31, gid = L>>2, t = L&3;
    const int wm = w>>2, wn = w&3;
    const int m0 = blockIdx.y * 64;
    const int bx = blockIdx.x;

    const __half* Bmat;
    int nlocal0, ncout0;
    if (EPI == EPI_QKV) {
        Bmat = Bw + (size_t)(bx >> 1) * WSMALL;   // wq, wk, wv contiguous
        nlocal0 = (bx & 1) * 128;
        ncout0  = bx * 128;
    } else {
        Bmat = Bw;
        nlocal0 = bx * 128;
        ncout0  = nlocal0;
    }

    float acc[2][4][4];
    #pragma unroll
    for (int i = 0; i < 2; i++)
        #pragma unroll
        for (int j = 0; j < 4; j++)
            #pragma unroll
            for (int r = 0; r < 4; r++) acc[i][j][r] = 0.f;

    // A tile: 64 rows x 32 halves = 256 16B-chunks (1/thread)
    auto loadA = [&](int stg, int k0) {
        const int r = tid>>2, cc = (tid&3)*8;
        cp16(&As[stg*64 + r][cc], A + (size_t)(m0+r)*lda + k0 + cc);
    };
    // B tile: 128 rows x 32 halves = 512 chunks (2/thread)
    auto loadB = [&](int stg, int k0) {
        #pragma unroll
        for (int c = 0; c < 2; c++) {
            const int ci = tid*2 + c;
            const int r = ci>>2, cc = (ci&3)*8;
            cp16(&Bs[stg*128 + r][cc], Bmat + (size_t)(nlocal0+r)*ldb + k0 + cc);
        }
    };

    loadA(0, 0);  loadB(0, 0);  CP_COMMIT();
    loadA(1, 32); loadB(1, 32); CP_COMMIT();
    loadA(2, 64); loadB(2, 64); CP_COMMIT();

    // ldmatrix lane addressing (fp16 k16 fragments)
    const int rA = L & 15;
    const int wA = ((L>>4)&1)*8;
    const int rB = L & 7;
    const int wB = ((L>>3)&1)*8;

    const int iters = K/32;
    for (int it = 0; it < iters; it++) {
        asm volatile("cp.async.wait_group 2;");
        __syncthreads();

        const __half (*Ac)[40] = (const __half(*)[40])(As + (it&3)*64);
        const __half (*Bc)[40] = (const __half(*)[40])(Bs + (it&3)*128);

        #pragma unroll
        for (int kb = 0; kb < 2; kb++) {
            uint32_t af[2][4];
            #pragma unroll
            for (int mi = 0; mi < 2; mi++)
                ldsm_x4(af[mi], saddr(&Ac[wm*32 + mi*16 + rA][16*kb + wA]));
            #pragma unroll
            for (int nj = 0; nj < 4; nj++) {
                uint32_t bf[2];
                ldsm_x2(bf, saddr(&Bc[wn*32 + nj*8 + rB][16*kb + wB]));
                mma_f16(acc[0][nj], af[0], bf[0], bf[1]);
                mma_f16(acc[1][nj], af[1], bf[0], bf[1]);
            }
        }

        if (it + 3 < iters) {
            loadA((it+3)&3, (it+3)*32);
            loadB((it+3)&3, (it+3)*32);
            CP_COMMIT();
        }
    }

    // epilogue
    #pragma unroll
    for (int mi = 0; mi < 2; mi++) {
        #pragma unroll
        for (int half_ = 0; half_ < 2; half_++) {
            const int gm = m0 + wm*32 + mi*16 + gid + half_*8;
            #pragma unroll
            for (int nj = 0; nj < 4; nj++) {
                const int gc = ncout0 + wn*32 + nj*8 + 2*t;   // even
                float v0 = acc[mi][nj][half_*2 + 0];
                float v1 = acc[mi][nj][half_*2 + 1];

                if (EPI == EPI_QKV) {
                    if (ncout0 < 512) {
                        // Q or K: rope; Q additionally folds scale*log2e
                        const int s  = gm & (SEQ - 1);
                        const int dd = gc & (DHEAD - 1);
                        const float ang = (float)s * c_invfreq[dd >> 1];
                        float sn, cs;
                        sincosf(ang, &sn, &cs);
                        const float e = v0, o = v1;
                        v0 = e*cs - o*sn;
                        v1 = o*cs + e*sn;
                        __half2 hv;
                        if (ncout0 < 256) {
                            hv = __floats2half2_rn(v0*QSCALE, v1*QSCALE);
                            *(__half2*)&qh[(size_t)gm*DMODEL + gc] = hv;
                        } else {
                            hv = __floats2half2_rn(v0, v1);
                            *(__half2*)&kh[(size_t)gm*DMODEL + (gc - 256)] = hv;
                        }
                    } else {
                        // V: scatter transposed half into vt[b][h][d][s]
                        const int gc512 = gc - 512;
                        const int hh = gc512 >> 5, dd = gc512 & 31;
                        const size_t vb = (((size_t)(gm >> 12) * NHEAD + hh) * DHEAD + dd) * SEQ
                                          + (gm & (SEQ - 1));
                        vt[vb]       = __float2half_rn(v0);
                        vt[vb + SEQ] = __float2half_rn(v1);
                    }
                } else if (EPI == EPI_BIAS_GELU) {
                    float t0 = v0 + bias[gc], t1 = v1 + bias[gc + 1];
                    t0 = 0.5f * t0 * (1.0f + erff(t0 * 0.7071067811865476f));
                    t1 = 0.5f * t1 * (1.0f + erff(t1 * 0.7071067811865476f));
                    *(__half2*)&Ch[(size_t)gm*ldc + gc] = __floats2half2_rn(t0, t1);
                } else if (EPI == EPI_RESID) {
                    v0 += resid[(size_t)gm * ldr + gc];
                    v1 += resid[(size_t)gm * ldr + gc + 1];
                    *(float2*)&Cf[(size_t)gm*ldc + gc] = make_float2(v0, v1);
                } else {  // EPI_BIAS_RESID
                    v0 += bias[gc]     + resid[(size_t)gm * ldr + gc];
                    v1 += bias[gc + 1] + resid[(size_t)gm * ldr + gc + 1];
                    *(float2*)&Cf[(size_t)gm*ldc + gc] = make_float2(v0, v1);
                }
            }
        }
    }
}

// ---------------- Flash attention v7 ------------------------------------------
// fp16 QK^T + PV; softmax via ex2.f16x2 (half MUFU); psum via ones-row mma;
// ldsm_x4 paired b-frags. 128 q-rows, 8 warps, 3-stage pipeline.
__global__ __launch_bounds__(256, 3)
void flash_attn_v7(const __half* __restrict__ qh, const __half* __restrict__ kh,
                   const __half* __restrict__ vt, __half* __restrict__ out)
{
    extern __shared__ __half smh[];
    __half (*Qs)[40]  = (__half(*)[40])smh;                       // [128][40]
    __half (*Ks)[40]  = (__half(*)[40])(smh + 128*40);            // [3*64][40]
    __half (*Vts)[72] = (__half(*)[72])(smh + 128*40 + 3*64*40);  // [3*40][72]

    const int tid = threadIdx.x;
    const int w = tid>>5, L = tid&31, gid = L>>2, t = L&3;
    const int b = blockIdx.y >> 3, h = blockIdx.y & 7;
    const int qbase = blockIdx.x * 128;
    const int qw = w * 16;

    const __half* qg  = qh + (size_t)(b*SEQ + qbase)*DMODEL + h*32;
    const __half* kg  = kh + (size_t)(b*SEQ)*DMODEL + h*32;
    const __half* vtg = vt + (size_t)(b*NHEAD + h) * DHEAD * SEQ;

    // Q tile: 128 rows x 32 halves = 512 chunks (2/thread)
    #pragma unroll
    for (int c = 0; c < 2; c++) {
        const int ci = tid*2 + c;
        const int r = ci>>2, cc = (ci&3)*8;
        cp16(&Qs[r][cc], qg + (size_t)r*DMODEL + cc);
    }
    // ones/zeros rows d=32..39 of each V stage (row 32 = 1.0 -> psum via mma)
    for (int i = tid; i < 3*8*72; i += 256) {
        const int s = i / (8*72), rem = i % (8*72);
        const int r = rem / 72, c = rem % 72;
        Vts[s*40 + 32 + r][c] = (r == 0) ? __float2half(1.0f) : __float2half(0.0f);
    }
    auto loadKV = [&](int stg, int kt) {
        const int kbase = kt*64;
        {   // K: 64 rows x 32 halves = 256 chunks (1/thread)
            const int r = tid>>2, cc = (tid&3)*8;
            cp16(&Ks[stg*64 + r][cc], kg + (size_t)(kbase + r)*DMODEL + cc);
        }
        {   // V^T: 32 d-rows x 64 halves = 256 chunks (1/thread)
            const int d = tid>>3, ch = (tid&7)*8;
            cp16(&Vts[stg*40 + d][ch], vtg + (size_t)d*SEQ + kbase + ch);
        }
    };
    loadKV(0, 0); CP_COMMIT();
    loadKV(1, 1); CP_COMMIT();
    asm volatile("cp.async.wait_group 1;");
    __syncthreads();

    // hoist Q fragments: qa[kb][4], kb in {0,1} (k16 each)
    uint32_t qa[2][4];
    #pragma unroll
    for (int kb = 0; kb < 2; kb++)
        ldsm_x4(qa[kb], saddr(&Qs[qw + (L&15)][16*kb + ((L>>4)&1)*8]));

    // ldmatrix lane addressing
    const int rK  = L & 7;                         // x2 frags
    const int wK  = ((L>>3)&1)*8;
    const int rK4 = (L&7) + ((L>>4)&1)*8;          // x4 paired frags
    const int wK4 = ((L>>3)&1)*8;

    float oacc[5][4];
    #pragma unroll
    for (int j = 0; j < 5; j++)
        #pragma unroll
        for (int r = 0; r < 4; r++) oacc[j][r] = 0.f;
    float mA = -1e30f, mB = -1e30f;

    for (int kt = 0; kt < SEQ/64; kt++) {
        if (kt > 0) { asm volatile("cp.async.wait_group 1;"); }
        __syncthreads();
        if (kt + 2 < SEQ/64) { loadKV((kt+2)%3, kt+2); CP_COMMIT(); }

        const int stg = kt % 3;
        const __half (*Kc)[40]  = (const __half(*)[40])(Ks + stg*64);
        const __half (*Vc)[72]  = (const __half(*)[72])(Vts + stg*40);

        // S' = (Q*scale*log2e) K^T  (fp16 mma, fp32 acc); x4-paired K frags
        float sa[8][4];
        #pragma unroll
        for (int j = 0; j < 8; j++)
            #pragma unroll
            for (int r = 0; r < 4; r++) sa[j][r] = 0.f;

        #pragma unroll
        for (int kb = 0; kb < 2; kb++) {
            #pragma unroll
            for (int jp = 0; jp < 4; jp++) {
                uint32_t bf[4];
                ldsm_x4(bf, saddr(&Kc[16*jp + rK4][16*kb + wK4]));
                mma_f16(sa[2*jp    ], qa[kb], bf[0], bf[1]);
                mma_f16(sa[2*jp + 1], qa[kb], bf[2], bf[3]);
            }
        }

        // online softmax in log2 domain (rows gid [A], gid+8 [B])
        float mxA = -1e30f, mxB = -1e30f;
        #pragma unroll
        for (int j = 0; j < 8; j++) {
            mxA = fmaxf(mxA, fmaxf(sa[j][0], sa[j][1]));
            mxB = fmaxf(mxB, fmaxf(sa[j][2], sa[j][3]));
        }
        #pragma unroll
        for (int o = 1; o <= 2; o <<= 1) {
            mxA = fmaxf(mxA, __shfl_xor_sync(0xffffffffu, mxA, o));
            mxB = fmaxf(mxB, __shfl_xor_sync(0xffffffffu, mxB, o));
        }
        const float mnA = fmaxf(mA, mxA);
        const float mnB = fmaxf(mB, mxB);
        const float corrA = ex2(mA - mnA);
        const float corrB = ex2(mB - mnB);
        mA = mnA; mB = mnB;

        // p = ex2(s'-m'): f32 subtract, pack, ONE f16x2 MUFU per pair
        uint32_t pa[8][2];
        #pragma unroll
        for (int j = 0; j < 8; j++) {
            pa[j][0] = hex2(pack_f16(sa[j][0] - mA, sa[j][1] - mA));   // row gid
            pa[j][1] = hex2(pack_f16(sa[j][2] - mB, sa[j][3] - mB));   // row gid+8
        }
        #pragma unroll
        for (int j = 0; j < 5; j++) {
            oacc[j][0] *= corrA; oacc[j][1] *= corrA;
            oacc[j][2] *= corrB; oacc[j][3] *= corrB;
        }

        // O += P V (j=0..3) and l += P*ones (j=4) : fp16 mma
        #pragma unroll
        for (int ks = 0; ks < 4; ks++) {
            uint32_t af[4] = { pa[2*ks][0], pa[2*ks][1], pa[2*ks+1][0], pa[2*ks+1][1] };
            #pragma unroll
            for (int jp = 0; jp < 2; jp++) {
                uint32_t bf[4];
                ldsm_x4(bf, saddr(&Vc[16*jp + rK4][16*ks + wK4]));
                mma_f16(oacc[2*jp    ], af, bf[0], bf[1]);
                mma_f16(oacc[2*jp + 1], af, bf[2], bf[3]);
            }
            uint32_t bo[2];
            ldsm_x2(bo, saddr(&Vc[32 + rK][16*ks + wK]));
            mma_f16(oacc[4], af, bo[0], bo[1]);
        }
    }

    // l = row-sum lives in oacc[4][0] (A, lane t=0) / oacc[4][2] (B, lane t=0)
    float lA = oacc[4][0], lB = oacc[4][2];
    #pragma unroll
    for (int o = 1; o <= 2; o <<= 1) {
        lA += __shfl_xor_sync(0xffffffffu, lA, o);
        lB += __shfl_xor_sync(0xffffffffu, lB, o);
    }
    const float invA = 1.0f / lA;
    const float invB = 1.0f / lB;

    #pragma unroll
    for (int j = 0; j < 4; j++) {
        const int gc = h*32 + 8*j + 2*t;
        const int rA2 = b*SEQ + qbase + qw + gid;
        const int rB2 = rA2 + 8;
        *(__half2*)&out[(size_t)rA2 * DMODEL + gc] =
            __floats2half2_rn(oacc[j][0]*invA, oacc[j][1]*invA);
        *(__half2*)&out[(size_t)rB2 * DMODEL + gc] =
            __floats2half2_rn(oacc[j][2]*invB, oacc[j][3]*invB);
    }
}

// ---------------- launch ------------------------------------------------------
extern "C" void kernel_launch(void* const* d_in, const int* in_sizes, int n_in,
                              void* d_out, int out_size)
{
    const float* x     = (const float*)d_in[0];
    const float* Wq    = (const float*)d_in[1];
    const float* Wk    = (const float*)d_in[2];
    const float* Wv    = (const float*)d_in[3];
    const float* Wo    = (const float*)d_in[4];
    const float* ln1_g = (const float*)d_in[5];
    const float* ln1_b = (const float*)d_in[6];
    const float* ln2_g = (const float*)d_in[7];
    const float* ln2_b = (const float*)d_in[8];
    const float* W2    = (const float*)d_in[9];
    const float* b2    = (const float*)d_in[10];
    const float* W3    = (const float*)d_in[11];
    const float* b3    = (const float*)d_in[12];
    float* out = (float*)d_out;

    __half *xn, *qh, *kh, *vt, *attn, *yn, *hbuf, *wr;
    float *mlpin;
    cudaGetSymbolAddress((void**)&xn,    g_xn);
    cudaGetSymbolAddress((void**)&qh,    g_qh);
    cudaGetSymbolAddress((void**)&kh,    g_kh);
    cudaGetSymbolAddress((void**)&vt,    g_vt);
    cudaGetSymbolAddress((void**)&attn,  g_attn);
    cudaGetSymbolAddress((void**)&mlpin, g_mlpin);
    cudaGetSymbolAddress((void**)&yn,    g_yn);
    cudaGetSymbolAddress((void**)&hbuf,  g_hb);
    cudaGetSymbolAddress((void**)&wr,    g_wr);

    const __half* wr_q = wr;                       // wq, wk, wv contiguous
    const __half* wr_o = wr + 3*WSMALL;
    const __half* wr_2 = wr + 4*WSMALL;
    const __half* wr_3 = wr + 4*WSMALL + WBIG;

    const int smGemm = (4*64*40 + 4*128*40) * 2;                   // 61440
    const int smAttn = (128*40 + 3*64*40 + 3*40*72) * 2;           // 42880

    cudaFuncSetAttribute(gemm_h<EPI_QKV>,        cudaFuncAttributeMaxDynamicSharedMemorySize, smGemm);
    cudaFuncSetAttribute(gemm_h<EPI_BIAS_GELU>,  cudaFuncAttributeMaxDynamicSharedMemorySize, smGemm);
    cudaFuncSetAttribute(gemm_h<EPI_RESID>,      cudaFuncAttributeMaxDynamicSharedMemorySize, smGemm);
    cudaFuncSetAttribute(gemm_h<EPI_BIAS_RESID>, cudaFuncAttributeMaxDynamicSharedMemorySize, smGemm);
    cudaFuncSetAttribute(flash_attn_v7,          cudaFuncAttributeMaxDynamicSharedMemorySize, smAttn);

    // weight conversion (deterministic)
    round_weights<<<(4*WSMALL + 2*WBIG)/4/256, 256>>>(Wq, Wk, Wv, Wo, W2, W3, wr);

    // LN1 -> half
    ln_kernel<<<NROW, 256>>>(x, ln1_g, ln1_b, xn);

    // Fused QKV projections: Q (rope+scale), K (rope), V -> half V^T
    gemm_h<EPI_QKV><<<dim3(6, NROW/64), 256, smGemm>>>(
        xn, DMODEL, wr_q, DMODEL, DMODEL,
        nullptr, nullptr, 0, nullptr, nullptr, 0, qh, kh, vt);

    // attention -> half
    flash_attn_v7<<<dim3(SEQ/128, BATCH*NHEAD), 256, smAttn>>>(qh, kh, vt, attn);

    // output projection + residual -> mlp_in (fp32)
    gemm_h<EPI_RESID><<<dim3(2, NROW/64), 256, smGemm>>>(
        attn, DMODEL, wr_o, DMODEL, DMODEL,
        mlpin, nullptr, DMODEL, nullptr, x, DMODEL, nullptr, nullptr, nullptr);

    // LN2 -> half
    ln_kernel<<<NROW, 256>>>(mlpin, ln2_g, ln2_b, yn);

    // MLP
    gemm_h<EPI_BIAS_GELU><<<dim3(8, NROW/64), 256, smGemm>>>(
        yn, DMODEL, wr_2, DMODEL, DMODEL,
        nullptr, hbuf, DMLP, b2, nullptr, 0, nullptr, nullptr, nullptr);
    gemm_h<EPI_BIAS_RESID><<<dim3(2, NROW/64), 256, smGemm>>>(
        hbuf, DMLP, wr_3, DMLP, DMLP,
        out, nullptr, DMODEL, b3, mlpin, DMODEL, nullptr, nullptr, nullptr);
}

// round 14
// speedup vs baseline: 2.2600x; 1.0426x over previous
#include <cuda_runtime.h>
#include <cuda_fp16.h>
#include <math.h>
#include <stdint.h>

#define BATCH 2
#define SEQ   4096
#define DMODEL 256
#define NHEAD 8
#define DHEAD 32
#define DMLP  1024
#define NROW  (BATCH*SEQ)   // 8192

// ---------------- scratch (static device globals; no allocation) -------------
__device__ __half g_xn[NROW*DMODEL];
__device__ __half g_qh[NROW*DMODEL];                 // Q (rope+scale*log2e), half
__device__ __half g_kh[NROW*DMODEL];                 // K (rope), half
__device__ __half g_vt[BATCH*NHEAD*DHEAD*SEQ];       // V^T: [b][h][d][s], half
__device__ __half g_attn[NROW*DMODEL];
__device__ float  g_mlpin[NROW*DMODEL];
__device__ __half g_yn[NROW*DMODEL];
__device__ __half g_hb[NROW*DMLP];
#define WSMALL (DMODEL*DMODEL)        // 65536
#define WBIG   (DMLP*DMODEL)          // 262144
__device__ __half g_wr[4*WSMALL + 2*WBIG];           // half weights

// inv_freq[i] = 10000^(-i/16) = 10^(-i/4)
__constant__ float c_invfreq[16] = {
    1.0f, 0.5623413251903491f, 0.31622776601683794f, 0.17782794100389228f,
    0.1f, 0.05623413251903491f, 0.031622776601683794f, 0.017782794100389228f,
    0.01f, 0.005623413251903491f, 0.0031622776601683794f, 0.0017782794100389228f,
    0.001f, 0.0005623413251903491f, 0.00031622776601683794f, 0.00017782794100389227f
};

// (1/sqrt(32)) * log2(e): folded into Q so softmax runs in log2 domain
#define QSCALE 0.2550348754541408f

__device__ __forceinline__ float ex2(float x) {
    float y;
    asm("ex2.approx.f32 %0, %1;" : "=f"(y) : "f"(x));
    return y;
}
// pack two fp32 -> f16x2 (lo = first k, hi = second k)
__device__ __forceinline__ uint32_t pack_f16(float lo, float hi) {
    uint32_t r;
    asm("cvt.rn.f16x2.f32 %0, %1, %2;" : "=r"(r) : "f"(hi), "f"(lo));
    return r;
}
// two ex2 in one MUFU op
__device__ __forceinline__ uint32_t hex2(uint32_t x) {
    uint32_t r;
    asm("ex2.approx.f16x2 %0, %1;" : "=r"(r) : "r"(x));
    return r;
}
__device__ __forceinline__ void cp16(void* smem_dst, const void* gmem_src) {
    uint32_t s = (uint32_t)__cvta_generic_to_shared(smem_dst);
    asm volatile("cp.async.cg.shared.global [%0], [%1], 16;" :: "r"(s), "l"(gmem_src));
}
#define CP_COMMIT() asm volatile("cp.async.commit_group;")
__device__ __forceinline__ uint32_t saddr(const void* p) {
    return (uint32_t)__cvta_generic_to_shared(p);
}
__device__ __forceinline__ void ldsm_x4(uint32_t* r, uint32_t a) {
    asm volatile("ldmatrix.sync.aligned.m8n8.x4.shared.b16 {%0,%1,%2,%3}, [%4];"
        : "=r"(r[0]), "=r"(r[1]), "=r"(r[2]), "=r"(r[3]) : "r"(a));
}
__device__ __forceinline__ void ldsm_x2(uint32_t* r, uint32_t a) {
    asm volatile("ldmatrix.sync.aligned.m8n8.x2.shared.b16 {%0,%1}, [%2];"
        : "=r"(r[0]), "=r"(r[1]) : "r"(a));
}
// D += A*B, m16n8k16 fp16 inputs, fp32 accumulate
__device__ __forceinline__ void mma_f16(float* d, const uint32_t* a, uint32_t b0, uint32_t b1) {
    asm volatile("mma.sync.aligned.m16n8k16.row.col.f32.f16.f16.f32 "
        "{%0,%1,%2,%3}, {%4,%5,%6,%7}, {%8,%9}, {%0,%1,%2,%3};\n"
        : "+f"(d[0]), "+f"(d[1]), "+f"(d[2]), "+f"(d[3])
        : "r"(a[0]), "r"(a[1]), "r"(a[2]), "r"(a[3]), "r"(b0), "r"(b1));
}

// ---------------- weight conversion fp32 -> fp16 ------------------------------
__global__ void round_weights(const float* __restrict__ Wq, const float* __restrict__ Wk,
                              const float* __restrict__ Wv, const float* __restrict__ Wo,
                              const float* __restrict__ W2, const float* __restrict__ W3,
                              __half* __restrict__ out)
{
    const int i = blockIdx.x * blockDim.x + threadIdx.x;   // float4 index
    const int n1 = WSMALL / 4;
    const float4* src;
    int local;
    if (i < 4*n1) {
        const float* w4[4] = {Wq, Wk, Wv, Wo};
        src = (const float4*)w4[i / n1];
        local = i % n1;
    } else if (i < 4*n1 + WBIG/4) {
        src = (const float4*)W2; local = i - 4*n1;
    } else {
        src = (const float4*)W3; local = i - 4*n1 - WBIG/4;
    }
    float4 v = src[local];
    __half2 h0 = __floats2half2_rn(v.x, v.y);
    __half2 h1 = __floats2half2_rn(v.z, v.w);
    ((uint2*)out)[i] = make_uint2(*(uint32_t*)&h0, *(uint32_t*)&h1);
}

// ---------------- LayerNorm: one block per row, half output -------------------
__global__ void ln_kernel(const float* __restrict__ x, const float* __restrict__ g,
                          const float* __restrict__ b, __half* __restrict__ out)
{
    const int row = blockIdx.x;
    const int t   = threadIdx.x;
    const float v = x[row*DMODEL + t];
    __shared__ float red1[8];
    __shared__ float red2[8];

    float s = v;
    #pragma unroll
    for (int o = 16; o > 0; o >>= 1) s += __shfl_xor_sync(0xffffffffu, s, o);
    if ((t & 31) == 0) red1[t >> 5] = s;
    __syncthreads();
    float mean = 0.f;
    #pragma unroll
    for (int i = 0; i < 8; i++) mean += red1[i];
    mean *= (1.0f/DMODEL);
    const float d = v - mean;

    float s2 = d*d;
    #pragma unroll
    for (int o = 16; o > 0; o >>= 1) s2 += __shfl_xor_sync(0xffffffffu, s2, o);
    if ((t & 31) == 0) red2[t >> 5] = s2;
    __syncthreads();
    float var = 0.f;
    #pragma unroll
    for (int i = 0; i < 8; i++) var += red2[i];
    var *= (1.0f/DMODEL);

    out[row*DMODEL + t] = __float2half_rn(d * rsqrtf(var + 1e-5f) * g[t] + b[t]);
}

// ---------------- GEMM body (C = A * B^T), fp16 mma, 4-stage, paired ldsm -----
// Tile BMx128x32, 256 thr, 8 warps 2(m)x4(n), warp (BM/2)x32.
enum { EPI_QKV=0, EPI_BIAS_GELU=1, EPI_RESID=2, EPI_BIAS_RESID=3 };

template<int BM, int EPI>
__device__ __forceinline__
void gemm_body(const __half* __restrict__ A, int lda,
               const __half* __restrict__ Bw, int ldb,
               int K,
               float* __restrict__ Cf, __half* __restrict__ Ch, int ldc,
               const float* __restrict__ bias,
               const float* __restrict__ resid, int ldr,
               __half* __restrict__ qh, __half* __restrict__ kh, __half* __restrict__ vt)
{
    constexpr int MI2 = BM/32;
    extern __shared__ __half smh[];
    __half (*As)[40] = (__half(*)[40])smh;                 // [4*BM][40]
    __half (*Bs)[40] = (__half(*)[40])(smh + 4*BM*40);     // [4*128][40]

    const int tid = threadIdx.x;
    const int w = tid>>5, L = tid&31, gid = L>>2, t = L&3;
    const int wm = w>>2, wn = w&3;
    const int m0 = blockIdx.y * BM;
    const int bx = blockIdx.x;

    const __half* Bmat;
    int nlocal0, ncout0;
    if (EPI == EPI_QKV) {
        Bmat = Bw + (size_t)(bx >> 1) * WSMALL;   // wq, wk, wv contiguous
        nlocal0 = (bx & 1) * 128;
        ncout0  = bx * 128;
    } else {
        Bmat = Bw;
        nlocal0 = bx * 128;
        ncout0  = nlocal0;
    }

    float acc[MI2][4][4];
    #pragma unroll
    for (int i = 0; i < MI2; i++)
        #pragma unroll
        for (int j = 0; j < 4; j++)
            #pragma unroll
            for (int r = 0; r < 4; r++) acc[i][j][r] = 0.f;

    constexpr int ACH = BM/64;   // 16B chunks per thread for A tile
    auto loadA = [&](int stg, int k0) {
        #pragma unroll
        for (int c = 0; c < ACH; c++) {
            const int ci = tid*ACH + c;
            const int r = ci>>2, cc = (ci&3)*8;
            cp16(&As[stg*BM + r][cc], A + (size_t)(m0+r)*lda + k0 + cc);
        }
    };
    auto loadB = [&](int stg, int k0) {
        #pragma unroll
        for (int c = 0; c < 2; c++) {
            const int ci = tid*2 + c;
            const int r = ci>>2, cc = (ci&3)*8;
            cp16(&Bs[stg*128 + r][cc], Bmat + (size_t)(nlocal0+r)*ldb + k0 + cc);
        }
    };

    loadA(0, 0);  loadB(0, 0);  CP_COMMIT();
    loadA(1, 32); loadB(1, 32); CP_COMMIT();
    loadA(2, 64); loadB(2, 64); CP_COMMIT();

    // ldmatrix lane addressing
    const int rA  = L & 15;
    const int wA  = ((L>>4)&1)*8;
    const int rB4 = (L&7) + ((L>>4)&1)*8;   // paired-nj x4 frags
    const int wB4 = ((L>>3)&1)*8;

    const int iters = K/32;
    for (int it = 0; it < iters; it++) {
        asm volatile("cp.async.wait_group 2;");
        __syncthreads();

        const __half (*Ac)[40] = (const __half(*)[40])(As + (it&3)*BM);
        const __half (*Bc)[40] = (const __half(*)[40])(Bs + (it&3)*128);

        #pragma unroll
        for (int kb = 0; kb < 2; kb++) {
            uint32_t af[MI2][4];
            #pragma unroll
            for (int mi = 0; mi < MI2; mi++)
                ldsm_x4(af[mi], saddr(&Ac[wm*(BM/2) + mi*16 + rA][16*kb + wA]));
            #pragma unroll
            for (int jp = 0; jp < 2; jp++) {
                uint32_t bf[4];
                ldsm_x4(bf, saddr(&Bc[wn*32 + jp*16 + rB4][16*kb + wB4]));
                #pragma unroll
                for (int mi = 0; mi < MI2; mi++) {
                    mma_f16(acc[mi][2*jp    ], af[mi], bf[0], bf[1]);
                    mma_f16(acc[mi][2*jp + 1], af[mi], bf[2], bf[3]);
                }
            }
        }

        if (it + 3 < iters) {
            loadA((it+3)&3, (it+3)*32);
            loadB((it+3)&3, (it+3)*32);
            CP_COMMIT();
        }
    }

    // epilogue
    #pragma unroll
    for (int mi = 0; mi < MI2; mi++) {
        #pragma unroll
        for (int half_ = 0; half_ < 2; half_++) {
            const int gm = m0 + wm*(BM/2) + mi*16 + gid + half_*8;
            #pragma unroll
            for (int nj = 0; nj < 4; nj++) {
                const int gc = ncout0 + wn*32 + nj*8 + 2*t;   // even
                float v0 = acc[mi][nj][half_*2 + 0];
                float v1 = acc[mi][nj][half_*2 + 1];

                if (EPI == EPI_QKV) {
                    if (ncout0 < 512) {
                        // Q or K: rope; Q additionally folds scale*log2e
                        const int s  = gm & (SEQ - 1);
                        const int dd = gc & (DHEAD - 1);
                        const float ang = (float)s * c_invfreq[dd >> 1];
                        float sn, cs;
                        sincosf(ang, &sn, &cs);
                        const float e = v0, o = v1;
                        v0 = e*cs - o*sn;
                        v1 = o*cs + e*sn;
                        __half2 hv;
                        if (ncout0 < 256) {
                            hv = __floats2half2_rn(v0*QSCALE, v1*QSCALE);
                            *(__half2*)&qh[(size_t)gm*DMODEL + gc] = hv;
                        } else {
                            hv = __floats2half2_rn(v0, v1);
                            *(__half2*)&kh[(size_t)gm*DMODEL + (gc - 256)] = hv;
                        }
                    } else {
                        // V: scatter transposed half into vt[b][h][d][s]
                        const int gc512 = gc - 512;
                        const int hh = gc512 >> 5, dd = gc512 & 31;
                        const size_t vb = (((size_t)(gm >> 12) * NHEAD + hh) * DHEAD + dd) * SEQ
                                          + (gm & (SEQ - 1));
                        vt[vb]       = __float2half_rn(v0);
                        vt[vb + SEQ] = __float2half_rn(v1);
                    }
                } else if (EPI == EPI_BIAS_GELU) {
                    float t0 = v0 + bias[gc], t1 = v1 + bias[gc + 1];
                    t0 = 0.5f * t0 * (1.0f + erff(t0 * 0.7071067811865476f));
                    t1 = 0.5f * t1 * (1.0f + erff(t1 * 0.7071067811865476f));
                    *(__half2*)&Ch[(size_t)gm*ldc + gc] = __floats2half2_rn(t0, t1);
                } else if (EPI == EPI_RESID) {
                    v0 += resid[(size_t)gm * ldr + gc];
                    v1 += resid[(size_t)gm * ldr + gc + 1];
                    *(float2*)&Cf[(size_t)gm*ldc + gc] = make_float2(v0, v1);
                } else {  // EPI_BIAS_RESID
                    v0 += bias[gc]     + resid[(size_t)gm * ldr + gc];
                    v1 += bias[gc + 1] + resid[(size_t)gm * ldr + gc + 1];
                    *(float2*)&Cf[(size_t)gm*ldc + gc] = make_float2(v0, v1);
                }
            }
        }
    }
}

template<int EPI>
__global__ __launch_bounds__(256, 2)
void gemm128(const __half* A, int lda, const __half* Bw, int ldb, int K,
             float* Cf, __half* Ch, int ldc, const float* bias,
             const float* resid, int ldr, __half* qh, __half* kh, __half* vt)
{
    gemm_body<128, EPI>(A, lda, Bw, ldb, K, Cf, Ch, ldc, bias, resid, ldr, qh, kh, vt);
}
template<int EPI>
__global__ __launch_bounds__(256, 3)
void gemm64(const __half* A, int lda, const __half* Bw, int ldb, int K,
            float* Cf, __half* Ch, int ldc, const float* bias,
            const float* resid, int ldr, __half* qh, __half* kh, __half* vt)
{
    gemm_body<64, EPI>(A, lda, Bw, ldb, K, Cf, Ch, ldc, bias, resid, ldr, qh, kh, vt);
}

// ---------------- Flash attention v8 ------------------------------------------
// FA2-style: 4 warps x 32 q-rows (two m16 halves) -> K/V ldsm amortized 2x.
// fp16 QK^T + PV; ex2.f16x2 softmax; psum via ones-row mma; 3-stage pipeline.
__global__ __launch_bounds__(128, 3)
void flash_attn_v8(const __half* __restrict__ qh, const __half* __restrict__ kh,
                   const __half* __restrict__ vt, __half* __restrict__ out)
{
    extern __shared__ __half smh[];
    __half (*Qs)[40]  = (__half(*)[40])smh;                       // [128][40]
    __half (*Ks)[40]  = (__half(*)[40])(smh + 128*40);            // [3*64][40]
    __half (*Vts)[72] = (__half(*)[72])(smh + 128*40 + 3*64*40);  // [3*40][72]

    const int tid = threadIdx.x;
    const int w = tid>>5, L = tid&31, gid = L>>2, t = L&3;
    const int b = blockIdx.y >> 3, h = blockIdx.y & 7;
    const int qbase = blockIdx.x * 128;
    const int qw = w * 32;                       // 32 rows per warp

    const __half* qg  = qh + (size_t)(b*SEQ + qbase)*DMODEL + h*32;
    const __half* kg  = kh + (size_t)(b*SEQ)*DMODEL + h*32;
    const __half* vtg = vt + (size_t)(b*NHEAD + h) * DHEAD * SEQ;

    // Q tile: 128 rows x 4 chunks = 512 chunks (4/thread @128 thr)
    #pragma unroll
    for (int c = 0; c < 4; c++) {
        const int ci = tid*4 + c;
        const int r = ci>>2, cc = (ci&3)*8;
        cp16(&Qs[r][cc], qg + (size_t)r*DMODEL + cc);
    }
    // ones/zeros rows d=32..39 of each V stage (row 32 = 1.0 -> psum via mma)
    for (int i = tid; i < 3*8*72; i += 128) {
        const int s = i / (8*72), rem = i % (8*72);
        const int r = rem / 72, c = rem % 72;
        Vts[s*40 + 32 + r][c] = (r == 0) ? __float2half(1.0f) : __float2half(0.0f);
    }
    auto loadKV = [&](int stg, int kt) {
        const int kbase = kt*64;
        #pragma unroll
        for (int c = 0; c < 2; c++) {   // K: 256 chunks (2/thread)
            const int ci = tid*2 + c;
            const int r = ci>>2, cc = (ci&3)*8;
            cp16(&Ks[stg*64 + r][cc], kg + (size_t)(kbase + r)*DMODEL + cc);
        }
        #pragma unroll
        for (int c = 0; c < 2; c++) {   // V^T: 256 chunks (2/thread)
            const int ci = tid*2 + c;
            const int d = ci>>3, ch = (ci&7)*8;
            cp16(&Vts[stg*40 + d][ch], vtg + (size_t)d*SEQ + kbase + ch);
        }
    };
    loadKV(0, 0); CP_COMMIT();
    loadKV(1, 1); CP_COMMIT();
    asm volatile("cp.async.wait_group 1;");
    __syncthreads();

    // hoist Q fragments: qa[mi][kb][4] (two m16 halves, kb k16-steps)
    uint32_t qa[2][2][4];
    #pragma unroll
    for (int mi = 0; mi < 2; mi++)
        #pragma unroll
        for (int kb = 0; kb < 2; kb++)
            ldsm_x4(qa[mi][kb], saddr(&Qs[qw + mi*16 + (L&15)][16*kb + ((L>>4)&1)*8]));

    // ldmatrix lane addressing
    const int rK  = L & 7;
    const int wK  = ((L>>3)&1)*8;
    const int rK4 = (L&7) + ((L>>4)&1)*8;
    const int wK4 = ((L>>3)&1)*8;

    float oacc[2][5][4];
    #pragma unroll
    for (int mi = 0; mi < 2; mi++)
        #pragma unroll
        for (int j = 0; j < 5; j++)
            #pragma unroll
            for (int r = 0; r < 4; r++) oacc[mi][j][r] = 0.f;
    float mA[2] = {-1e30f, -1e30f}, mB[2] = {-1e30f, -1e30f};

    for (int kt = 0; kt < SEQ/64; kt++) {
        if (kt > 0) { asm volatile("cp.async.wait_group 1;"); }
        __syncthreads();
        if (kt + 2 < SEQ/64) { loadKV((kt+2)%3, kt+2); CP_COMMIT(); }

        const int stg = kt % 3;
        const __half (*Kc)[40]  = (const __half(*)[40])(Ks + stg*64);
        const __half (*Vc)[72]  = (const __half(*)[72])(Vts + stg*40);

        // S' = (Q*scale*log2e) K^T — K frags reused by both m-halves
        float sa[2][8][4];
        #pragma unroll
        for (int mi = 0; mi < 2; mi++)
            #pragma unroll
            for (int j = 0; j < 8; j++)
                #pragma unroll
                for (int r = 0; r < 4; r++) sa[mi][j][r] = 0.f;

        #pragma unroll
        for (int kb = 0; kb < 2; kb++) {
            #pragma unroll
            for (int jp = 0; jp < 4; jp++) {
                uint32_t bf[4];
                ldsm_x4(bf, saddr(&Kc[16*jp + rK4][16*kb + wK4]));
                #pragma unroll
                for (int mi = 0; mi < 2; mi++) {
                    mma_f16(sa[mi][2*jp    ], qa[mi][kb], bf[0], bf[1]);
                    mma_f16(sa[mi][2*jp + 1], qa[mi][kb], bf[2], bf[3]);
                }
            }
        }

        // online softmax per m-half (rows gid [A], gid+8 [B])
        uint32_t pa[2][8][2];
        float corrA[2], corrB[2];
        #pragma unroll
        for (int mi = 0; mi < 2; mi++) {
            float mxA = -1e30f, mxB = -1e30f;
            #pragma unroll
            for (int j = 0; j < 8; j++) {
                mxA = fmaxf(mxA, fmaxf(sa[mi][j][0], sa[mi][j][1]));
                mxB = fmaxf(mxB, fmaxf(sa[mi][j][2], sa[mi][j][3]));
            }
            #pragma unroll
            for (int o = 1; o <= 2; o <<= 1) {
                mxA = fmaxf(mxA, __shfl_xor_sync(0xffffffffu, mxA, o));
                mxB = fmaxf(mxB, __shfl_xor_sync(0xffffffffu, mxB, o));
            }
            const float mnA = fmaxf(mA[mi], mxA);
            const float mnB = fmaxf(mB[mi], mxB);
            corrA[mi] = ex2(mA[mi] - mnA);
            corrB[mi] = ex2(mB[mi] - mnB);
            mA[mi] = mnA; mB[mi] = mnB;

            #pragma unroll
            for (int j = 0; j < 8; j++) {
                pa[mi][j][0] = hex2(pack_f16(sa[mi][j][0] - mnA, sa[mi][j][1] - mnA));
                pa[mi][j][1] = hex2(pack_f16(sa[mi][j][2] - mnB, sa[mi][j][3] - mnB));
            }
            #pragma unroll
            for (int j = 0; j < 5; j++) {
                oacc[mi][j][0] *= corrA[mi]; oacc[mi][j][1] *= corrA[mi];
                oacc[mi][j][2] *= corrB[mi]; oacc[mi][j][3] *= corrB[mi];
            }
        }

        // O += P V (j=0..3) and l += P*ones (j=4); V frags reused by both halves
        #pragma unroll
        for (int ks = 0; ks < 4; ks++) {
            uint32_t af[2][4];
            #pragma unroll
            for (int mi = 0; mi < 2; mi++) {
                af[mi][0] = pa[mi][2*ks][0];   af[mi][1] = pa[mi][2*ks][1];
                af[mi][2] = pa[mi][2*ks+1][0]; af[mi][3] = pa[mi][2*ks+1][1];
            }
            #pragma unroll
            for (int jp = 0; jp < 2; jp++) {
                uint32_t bf[4];
                ldsm_x4(bf, saddr(&Vc[16*jp + rK4][16*ks + wK4]));
                #pragma unroll
                for (int mi = 0; mi < 2; mi++) {
                    mma_f16(oacc[mi][2*jp    ], af[mi], bf[0], bf[1]);
                    mma_f16(oacc[mi][2*jp + 1], af[mi], bf[2], bf[3]);
                }
            }
            uint32_t bo[2];
            ldsm_x2(bo, saddr(&Vc[32 + rK][16*ks + wK]));
            #pragma unroll
            for (int mi = 0; mi < 2; mi++)
                mma_f16(oacc[mi][4], af[mi], bo[0], bo[1]);
        }
    }

    // epilogue per m-half
    #pragma unroll
    for (int mi = 0; mi < 2; mi++) {
        float lA = oacc[mi][4][0], lB = oacc[mi][4][2];
        #pragma unroll
        for (int o = 1; o <= 2; o <<= 1) {
            lA += __shfl_xor_sync(0xffffffffu, lA, o);
            lB += __shfl_xor_sync(0xffffffffu, lB, o);
        }
        const float invA = 1.0f / lA;
        const float invB = 1.0f / lB;

        #pragma unroll
        for (int j = 0; j < 4; j++) {
            const int gc = h*32 + 8*j + 2*t;
            const int rA2 = b*SEQ + qbase + qw + mi*16 + gid;
            const int rB2 = rA2 + 8;
            *(__half2*)&out[(size_t)rA2 * DMODEL + gc] =
                __floats2half2_rn(oacc[mi][j][0]*invA, oacc[mi][j][1]*invA);
            *(__half2*)&out[(size_t)rB2 * DMODEL + gc] =
                __floats2half2_rn(oacc[mi][j][2]*invB, oacc[mi][j][3]*invB);
        }
    }
}

// ---------------- launch ------------------------------------------------------
extern "C" void kernel_launch(void* const* d_in, const int* in_sizes, int n_in,
                              void* d_out, int out_size)
{
    const float* x     = (const float*)d_in[0];
    const float* Wq    = (const float*)d_in[1];
    const float* Wk    = (const float*)d_in[2];
    const float* Wv    = (const float*)d_in[3];
    const float* Wo    = (const float*)d_in[4];
    const float* ln1_g = (const float*)d_in[5];
    const float* ln1_b = (const float*)d_in[6];
    const float* ln2_g = (const float*)d_in[7];
    const float* ln2_b = (const float*)d_in[8];
    const float* W2    = (const float*)d_in[9];
    const float* b2    = (const float*)d_in[10];
    const float* W3    = (const float*)d_in[11];
    const float* b3    = (const float*)d_in[12];
    float* out = (float*)d_out;

    __half *xn, *qh, *kh, *vt, *attn, *yn, *hbuf, *wr;
    float *mlpin;
    cudaGetSymbolAddress((void**)&xn,    g_xn);
    cudaGetSymbolAddress((void**)&qh,    g_qh);
    cudaGetSymbolAddress((void**)&kh,    g_kh);
    cudaGetSymbolAddress((void**)&vt,    g_vt);
    cudaGetSymbolAddress((void**)&attn,  g_attn);
    cudaGetSymbolAddress((void**)&mlpin, g_mlpin);
    cudaGetSymbolAddress((void**)&yn,    g_yn);
    cudaGetSymbolAddress((void**)&hbuf,  g_hb);
    cudaGetSymbolAddress((void**)&wr,    g_wr);

    const __half* wr_q = wr;                       // wq, wk, wv contiguous
    const __half* wr_o = wr + 3*WSMALL;
    const __half* wr_2 = wr + 4*WSMALL;
    const __half* wr_3 = wr + 4*WSMALL + WBIG;

    const int sm128 = (4*128*40 + 4*128*40) * 2;                   // 81920
    const int sm64  = (4*64*40  + 4*128*40) * 2;                   // 61440
    const int smAttn = (128*40 + 3*64*40 + 3*40*72) * 2;           // 42880

    cudaFuncSetAttribute(gemm128<EPI_QKV>,       cudaFuncAttributeMaxDynamicSharedMemorySize, sm128);
    cudaFuncSetAttribute(gemm128<EPI_BIAS_GELU>, cudaFuncAttributeMaxDynamicSharedMemorySize, sm128);
    cudaFuncSetAttribute(gemm64<EPI_RESID>,      cudaFuncAttributeMaxDynamicSharedMemorySize, sm64);
    cudaFuncSetAttribute(gemm64<EPI_BIAS_RESID>, cudaFuncAttributeMaxDynamicSharedMemorySize, sm64);
    cudaFuncSetAttribute(flash_attn_v8,          cudaFuncAttributeMaxDynamicSharedMemorySize, smAttn);

    // weight conversion (deterministic)
    round_weights<<<(4*WSMALL + 2*WBIG)/4/256, 256>>>(Wq, Wk, Wv, Wo, W2, W3, wr);

    // LN1 -> half
    ln_kernel<<<NROW, 256>>>(x, ln1_g, ln1_b, xn);

    // Fused QKV projections: Q (rope+scale), K (rope), V -> half V^T
    gemm128<EPI_QKV><<<dim3(6, NROW/128), 256, sm128>>>(
        xn, DMODEL, wr_q, DMODEL, DMODEL,
        nullptr, nullptr, 0, nullptr, nullptr, 0, qh, kh, vt);

    // attention -> half
    flash_attn_v8<<<dim3(SEQ/128, BATCH*NHEAD), 128, smAttn>>>(qh, kh, vt, attn);

    // output projection + residual -> mlp_in (fp32)
    gemm64<EPI_RESID><<<dim3(2, NROW/64), 256, sm64>>>(
        attn, DMODEL, wr_o, DMODEL, DMODEL,
        mlpin, nullptr, DMODEL, nullptr, x, DMODEL, nullptr, nullptr, nullptr);

    // LN2 -> half
    ln_kernel<<<NROW, 256>>>(mlpin, ln2_g, ln2_b, yn);

    // MLP
    gemm128<EPI_BIAS_GELU><<<dim3(8, NROW/128), 256, sm128>>>(
        yn, DMODEL, wr_2, DMODEL, DMODEL,
        nullptr, hbuf, DMLP, b2, nullptr, 0, nullptr, nullptr, nullptr);
    gemm64<EPI_BIAS_RESID><<<dim3(2, NROW/64), 256, sm64>>>(
        hbuf, DMLP, wr_3, DMLP, DMLP,
        out, nullptr, DMODEL, b3, mlpin, DMODEL, nullptr, nullptr, nullptr);
}